// round 7
// baseline (speedup 1.0000x reference)
#include <cuda_runtime.h>

#define NN 1024
#define EE 2048
#define CIN 4
#define HID 192
#define KCH 5
#define NL 4
#define NAUG 1152          // 5*HID (edge basis) + HID (root)
#define SA_STRIDE 132
#define SMEM_GEMM ((192*SA_STRIDE + 192*128)*4)   // 199680 bytes
#define SMEM_CHEB ((1024 + 16384 + 4096)*4)       // 86016

typedef unsigned long long ull;

// ---------------- device scratch (allocation-free) ----------------
__device__ float g_S[4*NN*CIN];       // S_k = lap(T_{k-1}), k=1..4
__device__ float g_h0[NN*HID];
__device__ float g_h1[NN*HID];
__device__ float g_Y[NN*NAUG];
__device__ float g_B[NL][HID*NAUG];   // B[i][j*1152 + k*192 + o]

// ---------------- f32x2 helpers ----------------
__device__ __forceinline__ void fma2(ull &c, ull a, ull b) {
    asm("fma.rn.f32x2 %0, %1, %2, %0;" : "+l"(c) : "l"(a), "l"(b));
}
__device__ __forceinline__ float2 up2(ull a) {
    float2 f; asm("mov.b64 {%0, %1}, %2;" : "=f"(f.x), "=f"(f.y) : "l"(a)); return f;
}

// ---------------- k_M: Mstack (36x4 blocks) + cheb prep (block 36,0) ----------------
__global__ void __launch_bounds__(256) k_M(const float* __restrict__ nn2_w,
                                           const float* __restrict__ nn2_b,
                                           const float* __restrict__ eenc_w,
                                           const float* __restrict__ eenc_b,
                                           const float* __restrict__ nn1_w,
                                           const float* __restrict__ nn1_b,
                                           const float* __restrict__ root_w,
                                           const int* __restrict__ ei,
                                           const float* __restrict__ x) {
    int t = threadIdx.x;
    if (blockIdx.x == 36) {
        if (blockIdx.y != 0) return;
        extern __shared__ float dsm[];
        float* sdeg = dsm;                 // [1024]
        float* sS   = dsm + 1024;          // [4][1024][4]
        float* sX   = dsm + 1024 + 16384;  // [1024][4]
        #pragma unroll
        for (int i = 0; i < 4; i++) sdeg[t + 256*i] = 0.f;
        #pragma unroll
        for (int i = 0; i < 64; i++) sS[t + 256*i] = 0.f;
        #pragma unroll
        for (int i = 0; i < 16; i++) sX[t + 256*i] = x[t + 256*i];
        __syncthreads();
        int s[8], d[8]; float w[8];
        #pragma unroll
        for (int j = 0; j < 8; j++) {
            int e = t*8 + j;
            s[j] = ei[e]; d[j] = ei[EE + e];
            atomicAdd(&sdeg[s[j]], 1.f);
        }
        __syncthreads();
        float dv[4];
        #pragma unroll
        for (int i = 0; i < 4; i++) dv[i] = sdeg[t + 256*i];
        __syncthreads();
        #pragma unroll
        for (int i = 0; i < 4; i++) sdeg[t + 256*i] = dv[i] > 0.f ? rsqrtf(dv[i]) : 0.f;
        __syncthreads();
        #pragma unroll
        for (int j = 0; j < 8; j++) w[j] = -sdeg[s[j]] * sdeg[d[j]];
        #pragma unroll
        for (int j = 0; j < 8; j++)
            #pragma unroll
            for (int c = 0; c < 4; c++)
                atomicAdd(&sS[d[j]*4 + c], w[j] * sX[s[j]*4 + c]);
        __syncthreads();
        #pragma unroll
        for (int j = 0; j < 8; j++)
            #pragma unroll
            for (int c = 0; c < 4; c++)
                atomicAdd(&sS[4096 + d[j]*4 + c], w[j] * sS[s[j]*4 + c]);
        __syncthreads();
        #pragma unroll
        for (int j = 0; j < 8; j++)
            #pragma unroll
            for (int c = 0; c < 4; c++)
                atomicAdd(&sS[8192 + d[j]*4 + c],
                          w[j] * (2.f*sS[4096 + s[j]*4 + c] - sX[s[j]*4 + c]));
        __syncthreads();
        #pragma unroll
        for (int j = 0; j < 8; j++)
            #pragma unroll
            for (int c = 0; c < 4; c++)
                atomicAdd(&sS[12288 + d[j]*4 + c],
                          w[j] * (2.f*sS[8192 + s[j]*4 + c] - sS[s[j]*4 + c]));
        __syncthreads();
        #pragma unroll
        for (int i = 0; i < 64; i++) g_S[t + 256*i] = sS[t + 256*i];
        return;
    }

    int i = blockIdx.y;
    __shared__ float2 sG[5*HID];
    if (t < HID) {
        float acc[5] = {0.f, 0.f, 0.f, 0.f, 0.f};
        const float* W = nn1_w + i*HID*HID;
        for (int j0 = 0; j0 < HID; j0++) {
            float w = W[j0*HID + t];
            acc[0] += eenc_w[j0]*w;
            acc[1] += eenc_w[HID + j0]*w;
            acc[2] += eenc_w[2*HID + j0]*w;
            acc[3] += eenc_w[3*HID + j0]*w;
            acc[4] += eenc_b[j0]*w;
        }
        acc[4] += nn1_b[i*HID + t];
        #pragma unroll
        for (int k = 0; k < 5; k++) sG[k*HID + t] = make_float2(acc[k], acc[k]);
    }
    {
        int m = blockIdx.x*1024 + t*4;
        int j = m / HID, o = m - j*HID;
        float4 v = *(const float4*)(root_w + (size_t)i*HID*HID + m);
        *(float4*)(g_B[i] + j*NAUG + 5*HID + o) = v;
    }
    __syncthreads();

    int m4 = (blockIdx.x*256 + t) * 4;
    const float* W = nn2_w + (size_t)i * HID * (HID*HID);
    ull acc[5][2] = {};
    #pragma unroll 4
    for (int j = 0; j < HID; j++) {
        float4 v = __ldg((const float4*)(W + (size_t)j*(HID*HID) + m4));
        ull v01, v23;
        asm("mov.b64 %0, {%1, %2};" : "=l"(v01) : "f"(v.x), "f"(v.y));
        asm("mov.b64 %0, {%1, %2};" : "=l"(v23) : "f"(v.z), "f"(v.w));
        #pragma unroll
        for (int k = 0; k < 5; k++) {
            ull gk = *(const ull*)&sG[k*HID + j];
            fma2(acc[k][0], gk, v01);
            fma2(acc[k][1], gk, v23);
        }
    }
    float4 b = __ldg((const float4*)(nn2_b + (size_t)i*(HID*HID) + m4));
    float2 a40 = up2(acc[4][0]), a41 = up2(acc[4][1]);
    a40.x += b.x; a40.y += b.y; a41.x += b.z; a41.y += b.w;
    int j2 = m4 / HID;
    int o  = m4 - j2 * HID;
    float* dst = g_B[i] + j2*NAUG + o;
    #pragma unroll
    for (int k = 0; k < 4; k++) {
        *(float2*)(dst + k*HID)     = up2(acc[k][0]);
        *(float2*)(dst + k*HID + 2) = up2(acc[k][1]);
    }
    *(float2*)(dst + 4*HID)     = a40;
    *(float2*)(dst + 4*HID + 2) = a41;
}

// ---------------- Cheb output: h0 = sum_k T_k @ W_k + b ----------------
__global__ void k_cheb_out(const float* __restrict__ x,
                           const float* __restrict__ cw, const float* __restrict__ cb) {
    int n = blockIdx.x, o = threadIdx.x;   // 1024 x 192
    __shared__ float tx[KCH][CIN];
    if (o < CIN) {
        float xv = x[n*CIN + o];
        float s1 = g_S[n*4+o], s2 = g_S[4096 + n*4+o];
        float s3 = g_S[2*4096 + n*4+o], s4 = g_S[3*4096 + n*4+o];
        tx[0][o] = xv;
        tx[1][o] = s1;
        tx[2][o] = 2.f*s2 - xv;
        tx[3][o] = 2.f*s3 - s1;
        tx[4][o] = 2.f*s4 - 2.f*s2 + xv;
    }
    __syncthreads();
    float acc = cb[o];
    #pragma unroll
    for (int k = 0; k < KCH; k++)
        #pragma unroll
        for (int c = 0; c < CIN; c++)
            acc += tx[k][c] * cw[(k*CIN + c)*HID + o];
    g_h0[n*HID + o] = acc;
}

// ---------------- fused LN + node GEMM (conflict-free prologue, M-packed f32x2) ----------------
__global__ void __launch_bounds__(256)
k_gemm(int layer, const float* __restrict__ lng, const float* __restrict__ lnb,
       const float* __restrict__ cb) {
    extern __shared__ float sm2[];
    float* sA  = sm2;                    // [192][132], bank(k,m) = (4k+m)%32
    float* sBd = sm2 + 192*SA_STRIDE;    // [192][128] duplicated (b,b) pairs
    __shared__ float slng[192], slnb[192];
    const float* hin  = (layer & 1) ? g_h1 : g_h0;
    float*       hout = (layer & 1) ? g_h0 : g_h1;
    const float* Bm = g_B[layer];
    int t = threadIdx.x;
    int m0 = blockIdx.x * 128;
    int n0 = blockIdx.y * 64;
    int do_ln = (layer > 0);
    int lane = t & 31, w = t >> 5;

    if (do_ln && t < 192) { slng[t] = lng[t]; slnb[t] = lnb[t]; }

    // phase 1: coalesced A load, transposed store (2-way max conflicts)
    {
        const float4* h4 = (const float4*)(hin + (size_t)m0*HID);
        int lm = (lane & 7) + 8*w;     // 0..63
        int lc = lane >> 3;            // 0..3
        #pragma unroll
        for (int i = 0; i < 12; i++) {
            #pragma unroll
            for (int half = 0; half < 2; half++) {
                int m  = lm + 64*half;
                int c4 = lc + 4*i;
                float4 v = h4[m*48 + c4];
                int k = c4*4;
                sA[(k+0)*SA_STRIDE + m] = v.x;
                sA[(k+1)*SA_STRIDE + m] = v.y;
                sA[(k+2)*SA_STRIDE + m] = v.z;
                sA[(k+3)*SA_STRIDE + m] = v.w;
            }
        }
    }
    __syncthreads();

    // phase 2: warps 0-3 LN in place (conflict-free column scans); warps 4-7 B load+dup
    if (t < 128) {
        if (do_ln) {
            int m = t;
            float s0=0.f, s1=0.f, s2=0.f, s3=0.f;
            #pragma unroll 4
            for (int k = 0; k < 192; k += 4) {
                s0 += sA[(k+0)*SA_STRIDE + m];
                s1 += sA[(k+1)*SA_STRIDE + m];
                s2 += sA[(k+2)*SA_STRIDE + m];
                s3 += sA[(k+3)*SA_STRIDE + m];
            }
            float mu = ((s0+s1)+(s2+s3)) * (1.f/192.f);
            float q0=0.f, q1=0.f, q2=0.f, q3=0.f;
            #pragma unroll 4
            for (int k = 0; k < 192; k += 4) {
                float d0 = sA[(k+0)*SA_STRIDE + m] - mu;
                float d1 = sA[(k+1)*SA_STRIDE + m] - mu;
                float d2 = sA[(k+2)*SA_STRIDE + m] - mu;
                float d3 = sA[(k+3)*SA_STRIDE + m] - mu;
                q0 = fmaf(d0,d0,q0); q1 = fmaf(d1,d1,q1);
                q2 = fmaf(d2,d2,q2); q3 = fmaf(d3,d3,q3);
            }
            float rs = rsqrtf(((q0+q1)+(q2+q3))*(1.f/192.f) + 1e-5f);
            #pragma unroll 4
            for (int k = 0; k < 192; k++) {
                float v = (sA[k*SA_STRIDE + m] - mu)*rs*slng[k] + slnb[k];
                sA[k*SA_STRIDE + m] = fmaxf(v, 0.f);
            }
        }
    } else {
        int tb = t - 128;
        // B tile: 192 rows x 64 cols = 6144 float2 -> 48 per loader thread
        #pragma unroll 8
        for (int i = 0; i < 48; i++) {
            int f = tb + 128*i;
            int kk = f >> 5, ch = f & 31;
            float2 v = __ldg((const float2*)(Bm + kk*NAUG + n0 + ch*2));
            *(float4*)&sBd[kk*128 + ch*4] = make_float4(v.x, v.x, v.y, v.y);
        }
    }
    __syncthreads();

    // phase 3: 20-instr inner loop (4 LDS.128 + 16 FMA2), M-packed accumulators
    int tx = t & 15, ty = t >> 4;
    const float* aB = sA + ty*8;
    const float* bB = sBd + tx*8;
    ull acc[4][4] = {};
    #pragma unroll 4
    for (int kk = 0; kk < 192; kk++) {
        ulonglong2 a01 = *(const ulonglong2*)(aB + kk*SA_STRIDE);
        ulonglong2 a23 = *(const ulonglong2*)(aB + kk*SA_STRIDE + 4);
        ulonglong2 b01 = *(const ulonglong2*)(bB + kk*128);
        ulonglong2 b23 = *(const ulonglong2*)(bB + kk*128 + 4);
        fma2(acc[0][0], a01.x, b01.x); fma2(acc[0][1], a01.x, b01.y);
        fma2(acc[0][2], a01.x, b23.x); fma2(acc[0][3], a01.x, b23.y);
        fma2(acc[1][0], a01.y, b01.x); fma2(acc[1][1], a01.y, b01.y);
        fma2(acc[1][2], a01.y, b23.x); fma2(acc[1][3], a01.y, b23.y);
        fma2(acc[2][0], a23.x, b01.x); fma2(acc[2][1], a23.x, b01.y);
        fma2(acc[2][2], a23.x, b23.x); fma2(acc[2][3], a23.x, b23.y);
        fma2(acc[3][0], a23.y, b01.x); fma2(acc[3][1], a23.y, b01.y);
        fma2(acc[3][2], a23.y, b23.x); fma2(acc[3][3], a23.y, b23.y);
    }

    // epilogue
    if (n0 < 5*HID) {
        #pragma unroll
        for (int pm = 0; pm < 4; pm++) {
            int m = m0 + ty*8 + pm*2;
            float2 c0 = up2(acc[pm][0]), c1 = up2(acc[pm][1]);
            float2 c2 = up2(acc[pm][2]), c3 = up2(acc[pm][3]);
            *(float4*)(g_Y + (size_t)m*NAUG + n0 + tx*4)     = make_float4(c0.x, c1.x, c2.x, c3.x);
            *(float4*)(g_Y + (size_t)(m+1)*NAUG + n0 + tx*4) = make_float4(c0.y, c1.y, c2.y, c3.y);
        }
    } else {
        int ob = n0 - 5*HID + tx*4;
        float4 cv = *(const float4*)(cb + ob);
        #pragma unroll
        for (int pm = 0; pm < 4; pm++) {
            int m = m0 + ty*8 + pm*2;
            float2 c0 = up2(acc[pm][0]), c1 = up2(acc[pm][1]);
            float2 c2 = up2(acc[pm][2]), c3 = up2(acc[pm][3]);
            float4 r0 = make_float4(c0.x + cv.x, c1.x + cv.y, c2.x + cv.z, c3.x + cv.w);
            float4 r1 = make_float4(c0.y + cv.x, c1.y + cv.y, c2.y + cv.z, c3.y + cv.w);
            if (do_ln) {  // residual (layers 1..3)
                float4 h0v = *(const float4*)(hin + (size_t)m*HID + ob);
                float4 h1v = *(const float4*)(hin + (size_t)(m+1)*HID + ob);
                r0.x += h0v.x; r0.y += h0v.y; r0.z += h0v.z; r0.w += h0v.w;
                r1.x += h1v.x; r1.y += h1v.y; r1.z += h1v.z; r1.w += h1v.w;
            }
            *(float4*)(hout + (size_t)m*HID + ob)     = r0;
            *(float4*)(hout + (size_t)(m+1)*HID + ob) = r1;
        }
    }
}

// ---------------- per-edge combine + scatter (vectorized, 4 edges/block) ----------------
__global__ void k_escatter(int layer, const int* __restrict__ ei, const float* __restrict__ attr) {
    float* hout = (layer & 1) ? g_h0 : g_h1;
    int t = threadIdx.x;                  // 192
    int e = blockIdx.x*4 + (t / 48);      // 512 blocks
    int o4 = t % 48;
    int s = ei[e], d = ei[EE + e];
    float4 a = __ldg((const float4*)(attr + e*4));
    const float4* Ys = (const float4*)(g_Y + (size_t)s*NAUG);
    float4 y0 = Ys[o4], y1 = Ys[48 + o4], y2 = Ys[96 + o4], y3 = Ys[144 + o4], y4 = Ys[192 + o4];
    float4 v;
    v.x = y4.x + a.x*y0.x + a.y*y1.x + a.z*y2.x + a.w*y3.x;
    v.y = y4.y + a.x*y0.y + a.y*y1.y + a.z*y2.y + a.w*y3.y;
    v.z = y4.z + a.x*y0.z + a.y*y1.z + a.z*y2.z + a.w*y3.z;
    v.w = y4.w + a.x*y0.w + a.y*y1.w + a.z*y2.w + a.w*y3.w;
    float* hp = hout + (size_t)d*HID + o4*4;
    atomicAdd(hp+0, v.x); atomicAdd(hp+1, v.y);
    atomicAdd(hp+2, v.z); atomicAdd(hp+3, v.w);
}

// ---------------- fused final LN + head ----------------
__global__ void k_out(const float* __restrict__ lng, const float* __restrict__ lnb,
                      const float* __restrict__ ow, const float* __restrict__ ob,
                      float* __restrict__ out) {
    int n = blockIdx.x, t = threadIdx.x;    // 1024 x 192
    __shared__ float red[6];
    __shared__ float r0s[6], r1s[6];
    int warp = t >> 5, lane = t & 31;
    float v = g_h0[n*HID + t];
    float s = v;
    #pragma unroll
    for (int o = 16; o > 0; o >>= 1) s += __shfl_xor_sync(0xffffffffu, s, o);
    if (lane == 0) red[warp] = s;
    __syncthreads();
    float tot = 0.f;
    #pragma unroll
    for (int w = 0; w < 6; w++) tot += red[w];
    float mu = tot * (1.f/192.f);
    float d = v - mu;
    float s2 = d * d;
    #pragma unroll
    for (int o = 16; o > 0; o >>= 1) s2 += __shfl_xor_sync(0xffffffffu, s2, o);
    __syncthreads();
    if (lane == 0) red[warp] = s2;
    __syncthreads();
    float var = 0.f;
    #pragma unroll
    for (int w = 0; w < 6; w++) var += red[w];
    var *= (1.f/192.f);
    float z = fmaxf(0.f, d * rsqrtf(var + 1e-5f) * lng[t] + lnb[t]);
    float p0 = z * ow[t*2];
    float p1 = z * ow[t*2 + 1];
    #pragma unroll
    for (int o = 16; o > 0; o >>= 1) {
        p0 += __shfl_xor_sync(0xffffffffu, p0, o);
        p1 += __shfl_xor_sync(0xffffffffu, p1, o);
    }
    if (lane == 0) { r0s[warp] = p0; r1s[warp] = p1; }
    __syncthreads();
    if (t == 0) {
        float a0 = ob[0], a1 = ob[1];
        #pragma unroll
        for (int w = 0; w < 6; w++) { a0 += r0s[w]; a1 += r1s[w]; }
        out[n*2]     = a0;
        out[n*2 + 1] = a1;
    }
}

// ---------------- launcher ----------------
extern "C" void kernel_launch(void* const* d_in, const int* in_sizes, int n_in,
                              void* d_out, int out_size) {
    const float* x       = (const float*)d_in[0];
    const int*   ei      = (const int*)  d_in[1];
    const float* attr    = (const float*)d_in[2];
    const float* cheb_w  = (const float*)d_in[4];
    const float* cheb_b  = (const float*)d_in[5];
    const float* eenc_w  = (const float*)d_in[6];
    const float* eenc_b  = (const float*)d_in[7];
    const float* nn1_w   = (const float*)d_in[8];
    const float* nn1_b   = (const float*)d_in[9];
    const float* nn2_w   = (const float*)d_in[10];
    const float* nn2_b   = (const float*)d_in[11];
    const float* root_w  = (const float*)d_in[12];
    const float* conv_b  = (const float*)d_in[13];
    const float* ln_g    = (const float*)d_in[14];
    const float* ln_b    = (const float*)d_in[15];
    const float* out_w   = (const float*)d_in[16];
    const float* out_b   = (const float*)d_in[17];
    float* out = (float*)d_out;

    cudaFuncSetAttribute(k_gemm, cudaFuncAttributeMaxDynamicSharedMemorySize, SMEM_GEMM);
    cudaFuncSetAttribute(k_M,    cudaFuncAttributeMaxDynamicSharedMemorySize, SMEM_CHEB);

    // Mstack + cheb prep (cheb block hides under the HBM stream)
    k_M<<<dim3(37, NL), 256, SMEM_CHEB>>>(nn2_w, nn2_b, eenc_w, eenc_b,
                                          nn1_w, nn1_b, root_w, ei, x);
    k_cheb_out<<<NN, HID>>>(x, cheb_w, cheb_b);

    // 4 NNConv layers
    for (int i = 0; i < NL; i++) {
        k_gemm<<<dim3(8, 18), 256, SMEM_GEMM>>>(i, ln_g + i*HID, ln_b + i*HID,
                                                conv_b + i*HID);
        k_escatter<<<512, 192>>>(i, ei, attr);
    }

    // fused final LN + head
    k_out<<<NN, HID>>>(ln_g, ln_b, out_w, out_b, out);
}

// round 9
// speedup vs baseline: 1.0179x; 1.0179x over previous
#include <cuda_runtime.h>
#include <cuda_bf16.h>

#define NN 1024
#define EE 2048
#define CIN 4
#define HID 192
#define KCH 5
#define NL 4
#define NAUG 1152          // 5*HID (edge basis) + HID (root)

// k_gemm smem: padded rows of 200 bf16 (400 B) -> conflict-free ldmatrix
#define ROWB 400
#define A1_OFF 0
#define A2_OFF 51200
#define B1_OFF 102400
#define B2_OFF 128000
#define SMEM_TC 153600
#define SMEM_CHEB ((1024 + 16384 + 4096)*4)   // 86016

typedef unsigned long long ull;

// ---------------- device scratch (allocation-free) ----------------
__device__ float g_S[4*NN*CIN];
__device__ float g_h0[NN*HID];
__device__ float g_h1[NN*HID];
__device__ float g_Y[NN*NAUG];
__device__ __nv_bfloat16 g_Bh1[NL*NAUG*HID];   // [layer][n][k] hi split
__device__ __nv_bfloat16 g_Bh2[NL*NAUG*HID];   // lo split

// ---------------- helpers ----------------
__device__ __forceinline__ void fma2(ull &c, ull a, ull b) {
    asm("fma.rn.f32x2 %0, %1, %2, %0;" : "+l"(c) : "l"(a), "l"(b));
}
__device__ __forceinline__ float2 up2(ull a) {
    float2 f; asm("mov.b64 {%0, %1}, %2;" : "=f"(f.x), "=f"(f.y) : "l"(a)); return f;
}
__device__ __forceinline__ unsigned s2u(const void* p) {
    unsigned a;
    asm("{ .reg .u64 t; cvta.to.shared.u64 t, %1; cvt.u32.u64 %0, t; }" : "=r"(a) : "l"(p));
    return a;
}
__device__ __forceinline__ void bsplit(float v, __nv_bfloat16 &b1, __nv_bfloat16 &b2) {
    b1 = __float2bfloat16(v);
    b2 = __float2bfloat16(v - __bfloat162float(b1));
}
__device__ __forceinline__ void ldsm4(unsigned &r0, unsigned &r1, unsigned &r2, unsigned &r3,
                                      unsigned addr) {
    asm volatile("ldmatrix.sync.aligned.m8n8.x4.shared.b16 {%0,%1,%2,%3}, [%4];"
                 : "=r"(r0), "=r"(r1), "=r"(r2), "=r"(r3) : "r"(addr));
}
__device__ __forceinline__ void mma_bf16(float* c,
                                         unsigned a0, unsigned a1, unsigned a2, unsigned a3,
                                         unsigned b0, unsigned b1) {
    asm volatile(
        "mma.sync.aligned.m16n8k16.row.col.f32.bf16.bf16.f32 "
        "{%0,%1,%2,%3}, {%4,%5,%6,%7}, {%8,%9}, {%0,%1,%2,%3};"
        : "+f"(c[0]), "+f"(c[1]), "+f"(c[2]), "+f"(c[3])
        : "r"(a0), "r"(a1), "r"(a2), "r"(a3), "r"(b0), "r"(b1));
}

// ---------------- k_M: Mstack->bf16 splits (36x4 blocks) + cheb prep (block 36,0) ----------------
__global__ void __launch_bounds__(256) k_M(const float* __restrict__ nn2_w,
                                           const float* __restrict__ nn2_b,
                                           const float* __restrict__ eenc_w,
                                           const float* __restrict__ eenc_b,
                                           const float* __restrict__ nn1_w,
                                           const float* __restrict__ nn1_b,
                                           const float* __restrict__ root_w,
                                           const int* __restrict__ ei,
                                           const float* __restrict__ x) {
    int t = threadIdx.x;
    if (blockIdx.x == 36) {
        if (blockIdx.y != 0) return;
        extern __shared__ float dsm[];
        float* sdeg = dsm;
        float* sS   = dsm + 1024;
        float* sX   = dsm + 1024 + 16384;
        #pragma unroll
        for (int i = 0; i < 4; i++) sdeg[t + 256*i] = 0.f;
        #pragma unroll
        for (int i = 0; i < 64; i++) sS[t + 256*i] = 0.f;
        #pragma unroll
        for (int i = 0; i < 16; i++) sX[t + 256*i] = x[t + 256*i];
        __syncthreads();
        int s[8], d[8]; float w[8];
        #pragma unroll
        for (int j = 0; j < 8; j++) {
            int e = t*8 + j;
            s[j] = ei[e]; d[j] = ei[EE + e];
            atomicAdd(&sdeg[s[j]], 1.f);
        }
        __syncthreads();
        float dv[4];
        #pragma unroll
        for (int i = 0; i < 4; i++) dv[i] = sdeg[t + 256*i];
        __syncthreads();
        #pragma unroll
        for (int i = 0; i < 4; i++) sdeg[t + 256*i] = dv[i] > 0.f ? rsqrtf(dv[i]) : 0.f;
        __syncthreads();
        #pragma unroll
        for (int j = 0; j < 8; j++) w[j] = -sdeg[s[j]] * sdeg[d[j]];
        #pragma unroll
        for (int j = 0; j < 8; j++)
            #pragma unroll
            for (int c = 0; c < 4; c++)
                atomicAdd(&sS[d[j]*4 + c], w[j] * sX[s[j]*4 + c]);
        __syncthreads();
        #pragma unroll
        for (int j = 0; j < 8; j++)
            #pragma unroll
            for (int c = 0; c < 4; c++)
                atomicAdd(&sS[4096 + d[j]*4 + c], w[j] * sS[s[j]*4 + c]);
        __syncthreads();
        #pragma unroll
        for (int j = 0; j < 8; j++)
            #pragma unroll
            for (int c = 0; c < 4; c++)
                atomicAdd(&sS[8192 + d[j]*4 + c],
                          w[j] * (2.f*sS[4096 + s[j]*4 + c] - sX[s[j]*4 + c]));
        __syncthreads();
        #pragma unroll
        for (int j = 0; j < 8; j++)
            #pragma unroll
            for (int c = 0; c < 4; c++)
                atomicAdd(&sS[12288 + d[j]*4 + c],
                          w[j] * (2.f*sS[8192 + s[j]*4 + c] - sS[s[j]*4 + c]));
        __syncthreads();
        #pragma unroll
        for (int i = 0; i < 64; i++) g_S[t + 256*i] = sS[t + 256*i];
        return;
    }

    int i = blockIdx.y;
    __shared__ float2 sG[5*HID];
    if (t < HID) {
        float acc[5] = {0.f, 0.f, 0.f, 0.f, 0.f};
        const float* W = nn1_w + i*HID*HID;
        for (int j0 = 0; j0 < HID; j0++) {
            float w = W[j0*HID + t];
            acc[0] += eenc_w[j0]*w;
            acc[1] += eenc_w[HID + j0]*w;
            acc[2] += eenc_w[2*HID + j0]*w;
            acc[3] += eenc_w[3*HID + j0]*w;
            acc[4] += eenc_b[j0]*w;
        }
        acc[4] += nn1_b[i*HID + t];
        #pragma unroll
        for (int k = 0; k < 5; k++) sG[k*HID + t] = make_float2(acc[k], acc[k]);
    }
    // root -> bf16 splits at n = 960..1151
    {
        int m = blockIdx.x*1024 + t*4;
        int j = m / HID, o = m - j*HID;
        float4 v = *(const float4*)(root_w + (size_t)i*HID*HID + m);
        float vv[4] = {v.x, v.y, v.z, v.w};
        #pragma unroll
        for (int e = 0; e < 4; e++) {
            size_t idx = ((size_t)i*NAUG + 5*HID + o + e)*HID + j;
            __nv_bfloat16 b1, b2;
            bsplit(vv[e], b1, b2);
            g_Bh1[idx] = b1; g_Bh2[idx] = b2;
        }
    }
    __syncthreads();

    int m4 = (blockIdx.x*256 + t) * 4;
    const float* W = nn2_w + (size_t)i * HID * (HID*HID);
    ull acc[5][2] = {};
    #pragma unroll 4
    for (int j = 0; j < HID; j++) {
        float4 v = __ldg((const float4*)(W + (size_t)j*(HID*HID) + m4));
        ull v01, v23;
        asm("mov.b64 %0, {%1, %2};" : "=l"(v01) : "f"(v.x), "f"(v.y));
        asm("mov.b64 %0, {%1, %2};" : "=l"(v23) : "f"(v.z), "f"(v.w));
        #pragma unroll
        for (int k = 0; k < 5; k++) {
            ull gk = *(const ull*)&sG[k*HID + j];
            fma2(acc[k][0], gk, v01);
            fma2(acc[k][1], gk, v23);
        }
    }
    float4 b = __ldg((const float4*)(nn2_b + (size_t)i*(HID*HID) + m4));
    int j2 = m4 / HID;
    int o  = m4 - j2 * HID;
    #pragma unroll
    for (int k = 0; k < 5; k++) {
        float2 p0 = up2(acc[k][0]), p1 = up2(acc[k][1]);
        float vv[4] = {p0.x, p0.y, p1.x, p1.y};
        if (k == 4) { vv[0] += b.x; vv[1] += b.y; vv[2] += b.z; vv[3] += b.w; }
        #pragma unroll
        for (int e = 0; e < 4; e++) {
            size_t idx = ((size_t)i*NAUG + k*HID + o + e)*HID + j2;
            __nv_bfloat16 b1, b2;
            bsplit(vv[e], b1, b2);
            g_Bh1[idx] = b1; g_Bh2[idx] = b2;
        }
    }
}

// ---------------- Cheb output: h0 = sum_k T_k @ W_k + b ----------------
__global__ void k_cheb_out(const float* __restrict__ x,
                           const float* __restrict__ cw, const float* __restrict__ cb) {
    int n = blockIdx.x, o = threadIdx.x;
    __shared__ float tx[KCH][CIN];
    if (o < CIN) {
        float xv = x[n*CIN + o];
        float s1 = g_S[n*4+o], s2 = g_S[4096 + n*4+o];
        float s3 = g_S[2*4096 + n*4+o], s4 = g_S[3*4096 + n*4+o];
        tx[0][o] = xv;
        tx[1][o] = s1;
        tx[2][o] = 2.f*s2 - xv;
        tx[3][o] = 2.f*s3 - s1;
        tx[4][o] = 2.f*s4 - 2.f*s2 + xv;
    }
    __syncthreads();
    float acc = cb[o];
    #pragma unroll
    for (int k = 0; k < KCH; k++)
        #pragma unroll
        for (int c = 0; c < CIN; c++)
            acc += tx[k][c] * cw[(k*CIN + c)*HID + o];
    g_h0[n*HID + o] = acc;
}

// ---------------- fused LN + HMMA bf16 split-GEMM ----------------
// Y[1024,1152] = LN(h_in) @ B  via A1B1 + A1B2 + A2B1 (mma.sync, fp32 reg accum)
__global__ void __launch_bounds__(256)
k_gemm(int layer, const float* __restrict__ lng, const float* __restrict__ lnb,
       const float* __restrict__ cb) {
    extern __shared__ char smc[];
    const float* hin  = (layer & 1) ? g_h1 : g_h0;
    float*       hout = (layer & 1) ? g_h0 : g_h1;
    int t = threadIdx.x;
    int wid = t >> 5, lane = t & 31;
    int m0 = blockIdx.x * 128;
    int n0 = blockIdx.y * 64;
    int do_ln = (layer > 0);
    unsigned sb = s2u(smc);

    // ---- A prologue: LN + bf16 split -> padded rows (2 threads per row) ----
    {
        int m = t >> 1, half = t & 1;
        const float4* rowp = (const float4*)(hin + (size_t)(m0 + m)*HID) + half*24;
        float mu = 0.f, rs = 0.f;
        if (do_ln) {
            float s = 0.f, q = 0.f;
            #pragma unroll 8
            for (int i = 0; i < 24; i++) {
                float4 v = __ldg(rowp + i);
                s += (v.x + v.y) + (v.z + v.w);
                q += v.x*v.x + v.y*v.y + v.z*v.z + v.w*v.w;
            }
            s += __shfl_xor_sync(0xffffffffu, s, 1);
            q += __shfl_xor_sync(0xffffffffu, q, 1);
            mu = s * (1.f/192.f);
            rs = rsqrtf(q*(1.f/192.f) - mu*mu + 1e-5f);
        }
        #pragma unroll 4
        for (int i = 0; i < 24; i++) {
            float4 v = __ldg(rowp + i);
            int k = half*96 + i*4;
            float vv[4] = {v.x, v.y, v.z, v.w};
            if (do_ln) {
                #pragma unroll
                for (int e = 0; e < 4; e++)
                    vv[e] = fmaxf(0.f, (vv[e] - mu)*rs*__ldg(lng + k + e) + __ldg(lnb + k + e));
            }
            __nv_bfloat16 h1[4], h2[4];
            #pragma unroll
            for (int e = 0; e < 4; e++) bsplit(vv[e], h1[e], h2[e]);
            #pragma unroll
            for (int p = 0; p < 2; p++) {
                unsigned off = m*ROWB + (k + p*2)*2;
                __nv_bfloat162 w1; w1.x = h1[p*2]; w1.y = h1[p*2+1];
                __nv_bfloat162 w2; w2.x = h2[p*2]; w2.y = h2[p*2+1];
                *(__nv_bfloat162*)(smc + A1_OFF + off) = w1;
                *(__nv_bfloat162*)(smc + A2_OFF + off) = w2;
            }
        }
    }
    // ---- B prologue: copy pre-split bf16 pairs into padded rows ----
    {
        const unsigned* B1 = (const unsigned*)(g_Bh1 + (size_t)layer*NAUG*HID);
        const unsigned* B2 = (const unsigned*)(g_Bh2 + (size_t)layer*NAUG*HID);
        #pragma unroll 4
        for (int i = 0; i < 24; i++) {
            int flat = t + 256*i;          // 0..6143
            int kp = flat % 96, nn = flat / 96;
            unsigned src = (unsigned)(((size_t)(n0 + nn)*HID) >> 1) + kp;
            unsigned off = nn*ROWB + kp*4;
            *(unsigned*)(smc + B1_OFF + off) = __ldg(B1 + src);
            *(unsigned*)(smc + B2_OFF + off) = __ldg(B2 + src);
        }
    }
    __syncthreads();

    // ---- HMMA main: 3 passes x 12 k16-steps ----
    int m0w = (wid & 3) * 32;
    int n0w = (wid >> 2) * 32;
    unsigned rA = sb + (unsigned)((m0w + (lane & 15))*ROWB + (lane >> 4)*16);
    unsigned rB = sb + (unsigned)((n0w + (lane & 15))*ROWB + (lane >> 4)*16);
    float acc[2][4][4] = {};
    #pragma unroll
    for (int pass = 0; pass < 3; pass++) {
        unsigned aBase = rA + ((pass == 2) ? A2_OFF : A1_OFF);
        unsigned bBase = rB + ((pass == 1) ? B2_OFF : B1_OFF);
        #pragma unroll
        for (int ks = 0; ks < 12; ks++) {
            unsigned ko = ks*32;
            unsigned a0,a1,a2,a3, a4,a5,a6,a7;
            unsigned b0,b1,b2,b3, b4,b5,b6,b7;
            ldsm4(a0,a1,a2,a3, aBase + ko);
            ldsm4(a4,a5,a6,a7, aBase + 16*ROWB + ko);
            ldsm4(b0,b1,b2,b3, bBase + ko);
            ldsm4(b4,b5,b6,b7, bBase + 16*ROWB + ko);
            mma_bf16(acc[0][0], a0,a1,a2,a3, b0,b2);
            mma_bf16(acc[0][1], a0,a1,a2,a3, b1,b3);
            mma_bf16(acc[0][2], a0,a1,a2,a3, b4,b6);
            mma_bf16(acc[0][3], a0,a1,a2,a3, b5,b7);
            mma_bf16(acc[1][0], a4,a5,a6,a7, b0,b2);
            mma_bf16(acc[1][1], a4,a5,a6,a7, b1,b3);
            mma_bf16(acc[1][2], a4,a5,a6,a7, b4,b6);
            mma_bf16(acc[1][3], a4,a5,a6,a7, b5,b7);
        }
    }

    // ---- epilogue: c frag [m=lane/4 (+8)][n=(lane%3)*2] ----
    int mr = m0 + m0w + (lane >> 2);
    int nc = (lane & 3) * 2;
    if (n0 < 5*HID) {
        #pragma unroll
        for (int mf = 0; mf < 2; mf++) {
            float* base = g_Y + (size_t)(mr + mf*16)*NAUG + n0 + n0w + nc;
            #pragma unroll
            for (int nf = 0; nf < 4; nf++) {
                *(float2*)(base + nf*8)            = make_float2(acc[mf][nf][0], acc[mf][nf][1]);
                *(float2*)(base + nf*8 + 8*NAUG)   = make_float2(acc[mf][nf][2], acc[mf][nf][3]);
            }
        }
    } else {
        int ob = n0 - 5*HID + n0w + nc;
        #pragma unroll
        for (int mf = 0; mf < 2; mf++) {
            int mA = mr + mf*16, mB = mA + 8;
            #pragma unroll
            for (int nf = 0; nf < 4; nf++) {
                int c = ob + nf*8;
                float2 r0 = make_float2(acc[mf][nf][0] + __ldg(cb + c),
                                        acc[mf][nf][1] + __ldg(cb + c + 1));
                float2 r1 = make_float2(acc[mf][nf][2] + __ldg(cb + c),
                                        acc[mf][nf][3] + __ldg(cb + c + 1));
                if (do_ln) {
                    float2 h0v = *(const float2*)(hin + (size_t)mA*HID + c);
                    float2 h1v = *(const float2*)(hin + (size_t)mB*HID + c);
                    r0.x += h0v.x; r0.y += h0v.y;
                    r1.x += h1v.x; r1.y += h1v.y;
                }
                *(float2*)(hout + (size_t)mA*HID + c) = r0;
                *(float2*)(hout + (size_t)mB*HID + c) = r1;
            }
        }
    }
}

// ---------------- per-edge combine + scatter ----------------
__global__ void k_escatter(int layer, const int* __restrict__ ei, const float* __restrict__ attr) {
    float* hout = (layer & 1) ? g_h0 : g_h1;
    int t = threadIdx.x;
    int e = blockIdx.x*4 + (t / 48);
    int o4 = t % 48;
    int s = ei[e], d = ei[EE + e];
    float4 a = __ldg((const float4*)(attr + e*4));
    const float4* Ys = (const float4*)(g_Y + (size_t)s*NAUG);
    float4 y0 = Ys[o4], y1 = Ys[48 + o4], y2 = Ys[96 + o4], y3 = Ys[144 + o4], y4 = Ys[192 + o4];
    float4 v;
    v.x = y4.x + a.x*y0.x + a.y*y1.x + a.z*y2.x + a.w*y3.x;
    v.y = y4.y + a.x*y0.y + a.y*y1.y + a.z*y2.y + a.w*y3.y;
    v.z = y4.z + a.x*y0.z + a.y*y1.z + a.z*y2.z + a.w*y3.z;
    v.w = y4.w + a.x*y0.w + a.y*y1.w + a.z*y2.w + a.w*y3.w;
    float* hp = hout + (size_t)d*HID + o4*4;
    atomicAdd(hp+0, v.x); atomicAdd(hp+1, v.y);
    atomicAdd(hp+2, v.z); atomicAdd(hp+3, v.w);
}

// ---------------- fused final LN + head ----------------
__global__ void k_out(const float* __restrict__ lng, const float* __restrict__ lnb,
                      const float* __restrict__ ow, const float* __restrict__ ob,
                      float* __restrict__ out) {
    int n = blockIdx.x, t = threadIdx.x;
    __shared__ float red[6];
    __shared__ float r0s[6], r1s[6];
    int warp = t >> 5, lane = t & 31;
    float v = g_h0[n*HID + t];
    float s = v;
    #pragma unroll
    for (int o = 16; o > 0; o >>= 1) s += __shfl_xor_sync(0xffffffffu, s, o);
    if (lane == 0) red[warp] = s;
    __syncthreads();
    float tot = 0.f;
    #pragma unroll
    for (int w = 0; w < 6; w++) tot += red[w];
    float mu = tot * (1.f/192.f);
    float d = v - mu;
    float s2 = d * d;
    #pragma unroll
    for (int o = 16; o > 0; o >>= 1) s2 += __shfl_xor_sync(0xffffffffu, s2, o);
    __syncthreads();
    if (lane == 0) red[warp] = s2;
    __syncthreads();
    float var = 0.f;
    #pragma unroll
    for (int w = 0; w < 6; w++) var += red[w];
    var *= (1.f/192.f);
    float z = fmaxf(0.f, d * rsqrtf(var + 1e-5f) * lng[t] + lnb[t]);
    float p0 = z * ow[t*2];
    float p1 = z * ow[t*2 + 1];
    #pragma unroll
    for (int o = 16; o > 0; o >>= 1) {
        p0 += __shfl_xor_sync(0xffffffffu, p0, o);
        p1 += __shfl_xor_sync(0xffffffffu, p1, o);
    }
    if (lane == 0) { r0s[warp] = p0; r1s[warp] = p1; }
    __syncthreads();
    if (t == 0) {
        float a0 = ob[0], a1 = ob[1];
        #pragma unroll
        for (int w = 0; w < 6; w++) { a0 += r0s[w]; a1 += r1s[w]; }
        out[n*2]     = a0;
        out[n*2 + 1] = a1;
    }
}

// ---------------- launcher ----------------
extern "C" void kernel_launch(void* const* d_in, const int* in_sizes, int n_in,
                              void* d_out, int out_size) {
    const float* x       = (const float*)d_in[0];
    const int*   ei      = (const int*)  d_in[1];
    const float* attr    = (const float*)d_in[2];
    const float* cheb_w  = (const float*)d_in[4];
    const float* cheb_b  = (const float*)d_in[5];
    const float* eenc_w  = (const float*)d_in[6];
    const float* eenc_b  = (const float*)d_in[7];
    const float* nn1_w   = (const float*)d_in[8];
    const float* nn1_b   = (const float*)d_in[9];
    const float* nn2_w   = (const float*)d_in[10];
    const float* nn2_b   = (const float*)d_in[11];
    const float* root_w  = (const float*)d_in[12];
    const float* conv_b  = (const float*)d_in[13];
    const float* ln_g    = (const float*)d_in[14];
    const float* ln_b    = (const float*)d_in[15];
    const float* out_w   = (const float*)d_in[16];
    const float* out_b   = (const float*)d_in[17];
    float* out = (float*)d_out;

    cudaFuncSetAttribute(k_gemm, cudaFuncAttributeMaxDynamicSharedMemorySize, SMEM_TC);
    cudaFuncSetAttribute(k_M,    cudaFuncAttributeMaxDynamicSharedMemorySize, SMEM_CHEB);

    // Mstack (bf16 splits) + cheb prep
    k_M<<<dim3(37, NL), 256, SMEM_CHEB>>>(nn2_w, nn2_b, eenc_w, eenc_b,
                                          nn1_w, nn1_b, root_w, ei, x);
    k_cheb_out<<<NN, HID>>>(x, cheb_w, cheb_b);

    // 4 NNConv layers: HMMA GEMM + edge combine/scatter
    for (int i = 0; i < NL; i++) {
        k_gemm<<<dim3(8, 18), 256, SMEM_TC>>>(i, ln_g + i*HID, ln_b + i*HID,
                                              conv_b + i*HID);
        k_escatter<<<512, 192>>>(i, ei, attr);
    }

    // fused final LN + head
    k_out<<<NN, HID>>>(ln_g, ln_b, out_w, out_b, out);
}

// round 10
// speedup vs baseline: 1.0390x; 1.0208x over previous
#include <cuda_runtime.h>

#define NN 1024
#define EE 2048
#define HID 192
#define KCH 5
#define NL 4
#define NAUG 1152
#define RA 132
#define RB 68
#define SMEM_MAIN ((192*RA + 2*192*RB)*4)          // 205824
#define SMEM_CHEB ((1024 + 16384 + 4096)*4)        // 86016

typedef unsigned long long ull;

// ---------------- device scratch (allocation-free) ----------------
__device__ float g_S[4*NN*4];
__device__ float g_h0[NN*HID];
__device__ float g_h1[NN*HID];
__device__ float g_Y[NN*NAUG];
__device__ float g_B[NL][HID*NAUG];   // [layer][k][n] fp32
__device__ unsigned g_bar;

// ---------------- helpers ----------------
__device__ __forceinline__ void fma2(ull &c, ull a, ull b) {
    asm("fma.rn.f32x2 %0, %1, %2, %0;" : "+l"(c) : "l"(a), "l"(b));
}
__device__ __forceinline__ float2 up2(ull a) {
    float2 f; asm("mov.b64 {%0, %1}, %2;" : "=f"(f.x), "=f"(f.y) : "l"(a)); return f;
}
__device__ __forceinline__ void gbar(unsigned target) {
    __threadfence();
    __syncthreads();
    if (threadIdx.x == 0) {
        atomicAdd(&g_bar, 1u);
        while (*((volatile unsigned*)&g_bar) < target) __nanosleep(64);
    }
    __syncthreads();
}

// ---------------- k_M: Mstack fp32 (36x4 blocks) + cheb prep (block 36,0) ----------------
__global__ void __launch_bounds__(256) k_M(const float* __restrict__ nn2_w,
                                           const float* __restrict__ nn2_b,
                                           const float* __restrict__ eenc_w,
                                           const float* __restrict__ eenc_b,
                                           const float* __restrict__ nn1_w,
                                           const float* __restrict__ nn1_b,
                                           const float* __restrict__ root_w,
                                           const int* __restrict__ ei,
                                           const float* __restrict__ x) {
    int t = threadIdx.x;
    if (blockIdx.x == 0 && blockIdx.y == 0 && t == 0) g_bar = 0;   // reset grid barrier
    if (blockIdx.x == 36) {
        if (blockIdx.y != 0) return;
        extern __shared__ float dsm[];
        float* sdeg = dsm;
        float* sS   = dsm + 1024;
        float* sX   = dsm + 1024 + 16384;
        #pragma unroll
        for (int i = 0; i < 4; i++) sdeg[t + 256*i] = 0.f;
        #pragma unroll
        for (int i = 0; i < 64; i++) sS[t + 256*i] = 0.f;
        #pragma unroll
        for (int i = 0; i < 16; i++) sX[t + 256*i] = x[t + 256*i];
        __syncthreads();
        int s[8], d[8]; float w[8];
        #pragma unroll
        for (int j = 0; j < 8; j++) {
            int e = t*8 + j;
            s[j] = ei[e]; d[j] = ei[EE + e];
            atomicAdd(&sdeg[s[j]], 1.f);
        }
        __syncthreads();
        float dv[4];
        #pragma unroll
        for (int i = 0; i < 4; i++) dv[i] = sdeg[t + 256*i];
        __syncthreads();
        #pragma unroll
        for (int i = 0; i < 4; i++) sdeg[t + 256*i] = dv[i] > 0.f ? rsqrtf(dv[i]) : 0.f;
        __syncthreads();
        #pragma unroll
        for (int j = 0; j < 8; j++) w[j] = -sdeg[s[j]] * sdeg[d[j]];
        #pragma unroll
        for (int j = 0; j < 8; j++)
            #pragma unroll
            for (int c = 0; c < 4; c++)
                atomicAdd(&sS[d[j]*4 + c], w[j] * sX[s[j]*4 + c]);
        __syncthreads();
        #pragma unroll
        for (int j = 0; j < 8; j++)
            #pragma unroll
            for (int c = 0; c < 4; c++)
                atomicAdd(&sS[4096 + d[j]*4 + c], w[j] * sS[s[j]*4 + c]);
        __syncthreads();
        #pragma unroll
        for (int j = 0; j < 8; j++)
            #pragma unroll
            for (int c = 0; c < 4; c++)
                atomicAdd(&sS[8192 + d[j]*4 + c],
                          w[j] * (2.f*sS[4096 + s[j]*4 + c] - sX[s[j]*4 + c]));
        __syncthreads();
        #pragma unroll
        for (int j = 0; j < 8; j++)
            #pragma unroll
            for (int c = 0; c < 4; c++)
                atomicAdd(&sS[12288 + d[j]*4 + c],
                          w[j] * (2.f*sS[8192 + s[j]*4 + c] - sS[s[j]*4 + c]));
        __syncthreads();
        #pragma unroll
        for (int i = 0; i < 64; i++) g_S[t + 256*i] = sS[t + 256*i];
        return;
    }

    int i = blockIdx.y;
    __shared__ float2 sG[5*HID];
    if (t < HID) {
        float acc[5] = {0.f, 0.f, 0.f, 0.f, 0.f};
        const float* W = nn1_w + i*HID*HID;
        for (int j0 = 0; j0 < HID; j0++) {
            float w = W[j0*HID + t];
            acc[0] += eenc_w[j0]*w;
            acc[1] += eenc_w[HID + j0]*w;
            acc[2] += eenc_w[2*HID + j0]*w;
            acc[3] += eenc_w[3*HID + j0]*w;
            acc[4] += eenc_b[j0]*w;
        }
        acc[4] += nn1_b[i*HID + t];
        #pragma unroll
        for (int k = 0; k < 5; k++) sG[k*HID + t] = make_float2(acc[k], acc[k]);
    }
    {
        int m = blockIdx.x*1024 + t*4;
        int j = m / HID, o = m - j*HID;
        float4 v = *(const float4*)(root_w + (size_t)i*HID*HID + m);
        *(float4*)(g_B[i] + j*NAUG + 5*HID + o) = v;
    }
    __syncthreads();

    int m4 = (blockIdx.x*256 + t) * 4;
    const float* W = nn2_w + (size_t)i * HID * (HID*HID);
    ull acc[5][2] = {};
    #pragma unroll 4
    for (int j = 0; j < HID; j++) {
        float4 v = __ldg((const float4*)(W + (size_t)j*(HID*HID) + m4));
        ull v01, v23;
        asm("mov.b64 %0, {%1, %2};" : "=l"(v01) : "f"(v.x), "f"(v.y));
        asm("mov.b64 %0, {%1, %2};" : "=l"(v23) : "f"(v.z), "f"(v.w));
        #pragma unroll
        for (int k = 0; k < 5; k++) {
            ull gk = *(const ull*)&sG[k*HID + j];
            fma2(acc[k][0], gk, v01);
            fma2(acc[k][1], gk, v23);
        }
    }
    float4 b = __ldg((const float4*)(nn2_b + (size_t)i*(HID*HID) + m4));
    float2 a40 = up2(acc[4][0]), a41 = up2(acc[4][1]);
    a40.x += b.x; a40.y += b.y; a41.x += b.z; a41.y += b.w;
    int j2 = m4 / HID;
    int o  = m4 - j2 * HID;
    float* dst = g_B[i] + j2*NAUG + o;
    #pragma unroll
    for (int k = 0; k < 4; k++) {
        *(float2*)(dst + k*HID)     = up2(acc[k][0]);
        *(float2*)(dst + k*HID + 2) = up2(acc[k][1]);
    }
    *(float2*)(dst + 4*HID)     = a40;
    *(float2*)(dst + 4*HID + 2) = a41;
}

// ---------------- persistent main kernel: cheb_out + 4x(LN-GEMM + escatter) + out ----------------
__global__ void __launch_bounds__(512, 1)
k_main(const float* __restrict__ x, const int* __restrict__ ei,
       const float* __restrict__ attr,
       const float* __restrict__ cw, const float* __restrict__ cbb,
       const float* __restrict__ conv_b,
       const float* __restrict__ lng, const float* __restrict__ lnb,
       const float* __restrict__ ow, const float* __restrict__ ob,
       float* __restrict__ out) {
    extern __shared__ float sm[];
    float* sA  = sm;                 // [192][RA] (a,a) dup pairs
    float* sB0 = sm + 192*RA;        // [192][RB] bank-staggered
    float* sB1 = sB0 + 192*RB;
    int t = threadIdx.x, b = blockIdx.x;

    // ---- phase: cheb_out -> g_h0 ----
    if (t < 384) {
        int g = t / 192, o = t - g*192;
        for (int i = 0; i < 4; i++) {
            int r = b*2 + g + 288*i;
            if (r < NN) {
                float acc = __ldg(cbb + o);
                #pragma unroll
                for (int c = 0; c < 4; c++) {
                    float xv = __ldg(x + r*4 + c);
                    float s1 = g_S[r*4+c],        s2 = g_S[4096 + r*4+c];
                    float s3 = g_S[8192 + r*4+c], s4 = g_S[12288 + r*4+c];
                    float t2 = 2.f*s2 - xv, t3 = 2.f*s3 - s1, t4 = 2.f*s4 - 2.f*s2 + xv;
                    acc += xv*__ldg(cw + c*HID + o)
                         + s1*__ldg(cw + (4+c)*HID + o)
                         + t2*__ldg(cw + (8+c)*HID + o)
                         + t3*__ldg(cw + (12+c)*HID + o)
                         + t4*__ldg(cw + (16+c)*HID + o);
                }
                g_h0[r*HID + o] = acc;
            }
        }
    }
    gbar(144u);

    int m0  = (b & 15) * 64;
    int njA = b >> 4;                // 0..8 ; partner n-tile njA+9

    for (int L = 0; L < NL; L++) {
        const float* hin  = (L & 1) ? g_h1 : g_h0;
        float*       hout = (L & 1) ? g_h0 : g_h1;
        const float* Bm = g_B[L];
        int do_ln = (L > 0);

        // ---- prologue: warps 0-3 LN+dup-A ; warps 4-15 load both B tiles ----
        if (t < 128) {
            int m = t >> 1, hf = t & 1;
            const float4* rp = (const float4*)(hin + (size_t)(m0 + m)*HID) + hf*24;
            float mu = 0.f, rs = 0.f;
            if (do_ln) {
                float s = 0.f, q = 0.f;
                #pragma unroll 8
                for (int i = 0; i < 24; i++) {
                    float4 v = __ldcv(rp + i);
                    s += (v.x + v.y) + (v.z + v.w);
                    q += v.x*v.x + v.y*v.y + v.z*v.z + v.w*v.w;
                }
                s += __shfl_xor_sync(0xffffffffu, s, 1);
                q += __shfl_xor_sync(0xffffffffu, q, 1);
                mu = s * (1.f/192.f);
                rs = rsqrtf(q*(1.f/192.f) - mu*mu + 1e-5f);
            }
            #pragma unroll 4
            for (int i = 0; i < 24; i++) {
                float4 v = __ldcv(rp + i);
                int k = hf*96 + i*4;
                float vv[4] = {v.x, v.y, v.z, v.w};
                #pragma unroll
                for (int e = 0; e < 4; e++) {
                    float z = vv[e];
                    if (do_ln)
                        z = fmaxf(0.f, (z - mu)*rs*__ldg(lng + L*HID + k + e)
                                        + __ldg(lnb + L*HID + k + e));
                    *(float2*)(sA + (k + e)*RA + 2*m) = make_float2(z, z);
                }
            }
        } else {
            int li = t - 128;
            #pragma unroll 4
            for (int i = 0; i < 16; i++) {
                int f = li + 384*i;                 // 0..6143
                int tile = f / 3072, r = f - tile*3072;
                int kk = r >> 4, w4 = r & 15;
                int nj = tile ? (njA + 9) : njA;
                float4 v = __ldg((const float4*)(Bm + kk*NAUG + nj*64 + w4*4));
                int w = w4*4;
                float* dst = (tile ? sB1 : sB0) + kk*RB + w + ((w >> 5) << 2);
                *(float4*)dst = v;
            }
        }
        __syncthreads();

        // ---- main: 3 LDS.128 + 8 FMA2 per kk ----
        {
            int half = t >> 8, th = t & 255;
            int tx = th & 7, ty = th >> 3;       // 8 n-groups x 32 m-pairs
            const float* sB = half ? sB1 : sB0;
            int nj = half ? (njA + 9) : njA;
            int w1 = tx*8;     int p1 = w1 + ((w1 >> 5) << 2);
            int w2 = tx*8 + 4; int p2 = w2 + ((w2 >> 5) << 2);
            ull acc[2][4] = {};
            #pragma unroll 4
            for (int kk = 0; kk < 192; kk++) {
                ulonglong2 av  = *(const ulonglong2*)(sA + kk*RA + ty*4);
                ulonglong2 b01 = *(const ulonglong2*)(sB + kk*RB + p1);
                ulonglong2 b23 = *(const ulonglong2*)(sB + kk*RB + p2);
                fma2(acc[0][0], av.x, b01.x); fma2(acc[0][1], av.x, b01.y);
                fma2(acc[0][2], av.x, b23.x); fma2(acc[0][3], av.x, b23.y);
                fma2(acc[1][0], av.y, b01.x); fma2(acc[1][1], av.y, b01.y);
                fma2(acc[1][2], av.y, b23.x); fma2(acc[1][3], av.y, b23.y);
            }
            int n0 = nj*64;
            if (nj < 15) {
                #pragma unroll
                for (int mi = 0; mi < 2; mi++) {
                    float* yp = g_Y + (size_t)(m0 + ty*2 + mi)*NAUG + n0 + tx*8;
                    float2 c0 = up2(acc[mi][0]), c1 = up2(acc[mi][1]);
                    float2 c2 = up2(acc[mi][2]), c3 = up2(acc[mi][3]);
                    *(float4*)yp       = make_float4(c0.x, c0.y, c1.x, c1.y);
                    *(float4*)(yp + 4) = make_float4(c2.x, c2.y, c3.x, c3.y);
                }
            } else {
                int ob2 = n0 - 960 + tx*8;
                float4 cb0 = *(const float4*)(conv_b + L*HID + ob2);
                float4 cb1 = *(const float4*)(conv_b + L*HID + ob2 + 4);
                #pragma unroll
                for (int mi = 0; mi < 2; mi++) {
                    int row = m0 + ty*2 + mi;
                    float2 c0 = up2(acc[mi][0]), c1 = up2(acc[mi][1]);
                    float2 c2 = up2(acc[mi][2]), c3 = up2(acc[mi][3]);
                    float4 r0 = make_float4(c0.x + cb0.x, c0.y + cb0.y, c1.x + cb0.z, c1.y + cb0.w);
                    float4 r1 = make_float4(c2.x + cb1.x, c2.y + cb1.y, c3.x + cb1.z, c3.y + cb1.w);
                    if (do_ln) {
                        float4 h0v = __ldcv((const float4*)(hin + (size_t)row*HID + ob2));
                        float4 h1v = __ldcv((const float4*)(hin + (size_t)row*HID + ob2 + 4));
                        r0.x += h0v.x; r0.y += h0v.y; r0.z += h0v.z; r0.w += h0v.w;
                        r1.x += h1v.x; r1.y += h1v.y; r1.z += h1v.z; r1.w += h1v.w;
                    }
                    *(float4*)(hout + (size_t)row*HID + ob2)     = r0;
                    *(float4*)(hout + (size_t)row*HID + ob2 + 4) = r1;
                }
            }
        }
        gbar(144u*(2 + 2*L));

        // ---- escatter: h[dst] += sum_k coef_k * Y[src, k*192+o] ----
        if (t < 384) {
            int g = t / 48, o4 = t - g*48;
            #pragma unroll
            for (int i = 0; i < 2; i++) {
                int e = b*8 + g + 1152*i;
                if (e < EE) {
                    int s = __ldg(ei + e), d = __ldg(ei + EE + e);
                    float4 a = __ldg((const float4*)(attr + e*4));
                    const float4* Ys = (const float4*)(g_Y + (size_t)s*NAUG);
                    float4 y0 = __ldcv(Ys + o4),       y1 = __ldcv(Ys + 48 + o4);
                    float4 y2 = __ldcv(Ys + 96 + o4),  y3 = __ldcv(Ys + 144 + o4);
                    float4 y4 = __ldcv(Ys + 192 + o4);
                    float4 v;
                    v.x = y4.x + a.x*y0.x + a.y*y1.x + a.z*y2.x + a.w*y3.x;
                    v.y = y4.y + a.x*y0.y + a.y*y1.y + a.z*y2.y + a.w*y3.y;
                    v.z = y4.z + a.x*y0.z + a.y*y1.z + a.z*y2.z + a.w*y3.z;
                    v.w = y4.w + a.x*y0.w + a.y*y1.w + a.z*y2.w + a.w*y3.w;
                    float* hp = hout + (size_t)d*HID + o4*4;
                    atomicAdd(hp+0, v.x); atomicAdd(hp+1, v.y);
                    atomicAdd(hp+2, v.z); atomicAdd(hp+3, v.w);
                }
            }
        }
        gbar(144u*(3 + 2*L));
    }

    // ---- phase: final LN + head (warp per row; h final = g_h0) ----
    {
        int w = t >> 5, l = t & 31;
        if (w < 8) {
            int r = b + 144*w;
            if (r < NN) {
                float v[6];
                #pragma unroll
                for (int j = 0; j < 6; j++) v[j] = __ldcv(g_h0 + r*HID + l + 32*j);
                float s = ((v[0]+v[1])+(v[2]+v[3]))+(v[4]+v[5]);
                float q = v[0]*v[0]+v[1]*v[1]+v[2]*v[2]+v[3]*v[3]+v[4]*v[4]+v[5]*v[5];
                #pragma unroll
                for (int o = 16; o > 0; o >>= 1) {
                    s += __shfl_xor_sync(0xffffffffu, s, o);
                    q += __shfl_xor_sync(0xffffffffu, q, o);
                }
                float mu = s * (1.f/192.f);
                float rs = rsqrtf(q*(1.f/192.f) - mu*mu + 1e-5f);
                float p0 = 0.f, p1 = 0.f;
                #pragma unroll
                for (int j = 0; j < 6; j++) {
                    int c = l + 32*j;
                    float z = fmaxf(0.f, (v[j] - mu)*rs*__ldg(lng + c) + __ldg(lnb + c));
                    p0 += z * __ldg(ow + c*2);
                    p1 += z * __ldg(ow + c*2 + 1);
                }
                #pragma unroll
                for (int o = 16; o > 0; o >>= 1) {
                    p0 += __shfl_xor_sync(0xffffffffu, p0, o);
                    p1 += __shfl_xor_sync(0xffffffffu, p1, o);
                }
                if (l == 0) {
                    out[r*2]     = p0 + __ldg(ob);
                    out[r*2 + 1] = p1 + __ldg(ob + 1);
                }
            }
        }
    }
}

// ---------------- launcher ----------------
extern "C" void kernel_launch(void* const* d_in, const int* in_sizes, int n_in,
                              void* d_out, int out_size) {
    const float* x       = (const float*)d_in[0];
    const int*   ei      = (const int*)  d_in[1];
    const float* attr    = (const float*)d_in[2];
    const float* cheb_w  = (const float*)d_in[4];
    const float* cheb_b  = (const float*)d_in[5];
    const float* eenc_w  = (const float*)d_in[6];
    const float* eenc_b  = (const float*)d_in[7];
    const float* nn1_w   = (const float*)d_in[8];
    const float* nn1_b   = (const float*)d_in[9];
    const float* nn2_w   = (const float*)d_in[10];
    const float* nn2_b   = (const float*)d_in[11];
    const float* root_w  = (const float*)d_in[12];
    const float* conv_b  = (const float*)d_in[13];
    const float* ln_g    = (const float*)d_in[14];
    const float* ln_b    = (const float*)d_in[15];
    const float* out_w   = (const float*)d_in[16];
    const float* out_b   = (const float*)d_in[17];
    float* out = (float*)d_out;

    cudaFuncSetAttribute(k_M,    cudaFuncAttributeMaxDynamicSharedMemorySize, SMEM_CHEB);
    cudaFuncSetAttribute(k_main, cudaFuncAttributeMaxDynamicSharedMemorySize, SMEM_MAIN);

    // launch 1: Mstack + cheb prep + barrier reset
    k_M<<<dim3(37, NL), 256, SMEM_CHEB>>>(nn2_w, nn2_b, eenc_w, eenc_b,
                                          nn1_w, nn1_b, root_w, ei, x);
    // launch 2: everything else, persistent with software grid barriers
    k_main<<<144, 512, SMEM_MAIN>>>(x, ei, attr, cheb_w, cheb_b, conv_b,
                                    ln_g, ln_b, out_w, out_b, out);
}

// round 12
// speedup vs baseline: 1.0710x; 1.0307x over previous
#include <cuda_runtime.h>

#define NN 1024
#define EE 2048
#define HID 192
#define KCH 5
#define NL 4
#define NAUG 1152
#define RA 132
#define RB 68
#define SMEM_MAIN ((192*RA + 2*192*RB)*4)          // 205824
#define SMEM_CHEB ((1024 + 16384 + 4096)*4)        // 86016

typedef unsigned long long ull;

// ---------------- device scratch (allocation-free) ----------------
__device__ float g_S[4*NN*4];
__device__ float g_h0[NN*HID];
__device__ float g_h1[NN*HID];
__device__ float g_Y[NN*NAUG];
__device__ float g_B[NL][HID*NAUG];   // [layer][k][n] fp32
__device__ unsigned g_bar;

// ---------------- helpers ----------------
__device__ __forceinline__ void fma2(ull &c, ull a, ull b) {
    asm("fma.rn.f32x2 %0, %1, %2, %0;" : "+l"(c) : "l"(a), "l"(b));
}
__device__ __forceinline__ float2 up2(ull a) {
    float2 f; asm("mov.b64 {%0, %1}, %2;" : "=f"(f.x), "=f"(f.y) : "l"(a)); return f;
}
__device__ __forceinline__ float4 ldcg4(const float4* p) { return __ldcg(p); }
__device__ __forceinline__ void gbar(unsigned target) {
    __threadfence();
    __syncthreads();
    if (threadIdx.x == 0) {
        atomicAdd(&g_bar, 1u);
        while (*((volatile unsigned*)&g_bar) < target) __nanosleep(32);
    }
    __syncthreads();
}

// ---------------- k_M: Mstack fp32 (36x4 blocks) + cheb prep (block 36,0) ----------------
__global__ void __launch_bounds__(256) k_M(const float* __restrict__ nn2_w,
                                           const float* __restrict__ nn2_b,
                                           const float* __restrict__ eenc_w,
                                           const float* __restrict__ eenc_b,
                                           const float* __restrict__ nn1_w,
                                           const float* __restrict__ nn1_b,
                                           const float* __restrict__ root_w,
                                           const int* __restrict__ ei,
                                           const float* __restrict__ x) {
    int t = threadIdx.x;
    if (blockIdx.x == 0 && blockIdx.y == 0 && t == 0) g_bar = 0;   // reset grid barrier
    if (blockIdx.x == 36) {
        if (blockIdx.y != 0) return;
        extern __shared__ float dsm[];
        float* sdeg = dsm;
        float* sS   = dsm + 1024;
        float* sX   = dsm + 1024 + 16384;
        #pragma unroll
        for (int i = 0; i < 4; i++) sdeg[t + 256*i] = 0.f;
        #pragma unroll
        for (int i = 0; i < 64; i++) sS[t + 256*i] = 0.f;
        #pragma unroll
        for (int i = 0; i < 16; i++) sX[t + 256*i] = x[t + 256*i];
        __syncthreads();
        int s[8], d[8]; float w[8];
        #pragma unroll
        for (int j = 0; j < 8; j++) {
            int e = t*8 + j;
            s[j] = ei[e]; d[j] = ei[EE + e];
            atomicAdd(&sdeg[s[j]], 1.f);
        }
        __syncthreads();
        float dv[4];
        #pragma unroll
        for (int i = 0; i < 4; i++) dv[i] = sdeg[t + 256*i];
        __syncthreads();
        #pragma unroll
        for (int i = 0; i < 4; i++) sdeg[t + 256*i] = dv[i] > 0.f ? rsqrtf(dv[i]) : 0.f;
        __syncthreads();
        #pragma unroll
        for (int j = 0; j < 8; j++) w[j] = -sdeg[s[j]] * sdeg[d[j]];
        #pragma unroll
        for (int j = 0; j < 8; j++)
            #pragma unroll
            for (int c = 0; c < 4; c++)
                atomicAdd(&sS[d[j]*4 + c], w[j] * sX[s[j]*4 + c]);
        __syncthreads();
        #pragma unroll
        for (int j = 0; j < 8; j++)
            #pragma unroll
            for (int c = 0; c < 4; c++)
                atomicAdd(&sS[4096 + d[j]*4 + c], w[j] * sS[s[j]*4 + c]);
        __syncthreads();
        #pragma unroll
        for (int j = 0; j < 8; j++)
            #pragma unroll
            for (int c = 0; c < 4; c++)
                atomicAdd(&sS[8192 + d[j]*4 + c],
                          w[j] * (2.f*sS[4096 + s[j]*4 + c] - sX[s[j]*4 + c]));
        __syncthreads();
        #pragma unroll
        for (int j = 0; j < 8; j++)
            #pragma unroll
            for (int c = 0; c < 4; c++)
                atomicAdd(&sS[12288 + d[j]*4 + c],
                          w[j] * (2.f*sS[8192 + s[j]*4 + c] - sS[s[j]*4 + c]));
        __syncthreads();
        #pragma unroll
        for (int i = 0; i < 64; i++) g_S[t + 256*i] = sS[t + 256*i];
        return;
    }

    int i = blockIdx.y;
    __shared__ float2 sG[5*HID];
    if (t < HID) {
        float acc[5] = {0.f, 0.f, 0.f, 0.f, 0.f};
        const float* W = nn1_w + i*HID*HID;
        for (int j0 = 0; j0 < HID; j0++) {
            float w = W[j0*HID + t];
            acc[0] += eenc_w[j0]*w;
            acc[1] += eenc_w[HID + j0]*w;
            acc[2] += eenc_w[2*HID + j0]*w;
            acc[3] += eenc_w[3*HID + j0]*w;
            acc[4] += eenc_b[j0]*w;
        }
        acc[4] += nn1_b[i*HID + t];
        #pragma unroll
        for (int k = 0; k < 5; k++) sG[k*HID + t] = make_float2(acc[k], acc[k]);
    }
    {
        int m = blockIdx.x*1024 + t*4;
        int j = m / HID, o = m - j*HID;
        float4 v = *(const float4*)(root_w + (size_t)i*HID*HID + m);
        *(float4*)(g_B[i] + j*NAUG + 5*HID + o) = v;
    }
    __syncthreads();

    int m4 = (blockIdx.x*256 + t) * 4;
    const float* W = nn2_w + (size_t)i * HID * (HID*HID);
    ull acc[5][2] = {};
    #pragma unroll 8
    for (int j = 0; j < HID; j++) {
        float4 v = __ldg((const float4*)(W + (size_t)j*(HID*HID) + m4));
        ull v01, v23;
        asm("mov.b64 %0, {%1, %2};" : "=l"(v01) : "f"(v.x), "f"(v.y));
        asm("mov.b64 %0, {%1, %2};" : "=l"(v23) : "f"(v.z), "f"(v.w));
        #pragma unroll
        for (int k = 0; k < 5; k++) {
            ull gk = *(const ull*)&sG[k*HID + j];
            fma2(acc[k][0], gk, v01);
            fma2(acc[k][1], gk, v23);
        }
    }
    float4 b = __ldg((const float4*)(nn2_b + (size_t)i*(HID*HID) + m4));
    float2 a40 = up2(acc[4][0]), a41 = up2(acc[4][1]);
    a40.x += b.x; a40.y += b.y; a41.x += b.z; a41.y += b.w;
    int j2 = m4 / HID;
    int o  = m4 - j2 * HID;
    float* dst = g_B[i] + j2*NAUG + o;
    #pragma unroll
    for (int k = 0; k < 4; k++) {
        *(float2*)(dst + k*HID)     = up2(acc[k][0]);
        *(float2*)(dst + k*HID + 2) = up2(acc[k][1]);
    }
    *(float2*)(dst + 4*HID)     = a40;
    *(float2*)(dst + 4*HID + 2) = a41;
}

// ---------------- persistent main kernel ----------------
__global__ void __launch_bounds__(512, 1)
k_main(const float* __restrict__ x, const int* __restrict__ ei,
       const float* __restrict__ attr,
       const float* __restrict__ cw, const float* __restrict__ cbb,
       const float* __restrict__ conv_b,
       const float* __restrict__ lng, const float* __restrict__ lnb,
       const float* __restrict__ ow, const float* __restrict__ ob,
       float* __restrict__ out) {
    extern __shared__ float sm[];
    float* sA  = sm;                 // [192][RA] (a,a) dup pairs
    float* sB0 = sm + 192*RA;        // [192][RB] bank-staggered
    float* sB1 = sB0 + 192*RB;
    int t = threadIdx.x, b = blockIdx.x;
    int m0  = (b & 15) * 64;
    int njA = b >> 4;                // 0..8 ; partner n-tile njA+9

    // ---- phase: cheb_out (t<384) + B-prefetch layer0 (t>=384) ----
    if (t < 384) {
        int g = t / 192, o = t - g*192;
        for (int i = 0; i < 4; i++) {
            int r = b*2 + g + 288*i;
            if (r < NN) {
                float acc = __ldg(cbb + o);
                #pragma unroll
                for (int c = 0; c < 4; c++) {
                    float xv = __ldg(x + r*4 + c);
                    float s1 = g_S[r*4+c],        s2 = g_S[4096 + r*4+c];
                    float s3 = g_S[8192 + r*4+c], s4 = g_S[12288 + r*4+c];
                    float t2 = 2.f*s2 - xv, t3 = 2.f*s3 - s1, t4 = 2.f*s4 - 2.f*s2 + xv;
                    acc += xv*__ldg(cw + c*HID + o)
                         + s1*__ldg(cw + (4+c)*HID + o)
                         + t2*__ldg(cw + (8+c)*HID + o)
                         + t3*__ldg(cw + (12+c)*HID + o)
                         + t4*__ldg(cw + (16+c)*HID + o);
                }
                g_h0[r*HID + o] = acc;
            }
        }
    } else {
        int li = t - 384;
        const float* Bm = g_B[0];
        #pragma unroll 4
        for (int i = 0; i < 48; i++) {
            int f = li + 128*i;
            int tile = f / 3072, r = f - tile*3072;
            int kk = r >> 4, w4 = r & 15;
            int nj = tile ? (njA + 9) : njA;
            float4 v = __ldg((const float4*)(Bm + kk*NAUG + nj*64 + w4*4));
            int w = w4*4;
            float* dst = (tile ? sB1 : sB0) + kk*RB + w + ((w >> 5) << 2);
            *(float4*)dst = v;
        }
    }
    gbar(144u);

    for (int L = 0; L < NL; L++) {
        const float* hin  = (L & 1) ? g_h1 : g_h0;
        float*       hout = (L & 1) ? g_h0 : g_h1;
        int do_ln = (L > 0);

        // ---- A prologue: 64 rows x 4 threads/row (t < 256), LN in registers ----
        if (t < 256) {
            int m = t >> 2, q = t & 3;
            const float4* rp = (const float4*)(hin + (size_t)(m0 + m)*HID) + q*12;
            float4 v[12];
            #pragma unroll
            for (int i = 0; i < 12; i++) v[i] = ldcg4(rp + i);
            float mu = 0.f, rs = 0.f;
            if (do_ln) {
                float s = 0.f, qq = 0.f;
                #pragma unroll
                for (int i = 0; i < 12; i++) {
                    s  += (v[i].x + v[i].y) + (v[i].z + v[i].w);
                    qq += v[i].x*v[i].x + v[i].y*v[i].y + v[i].z*v[i].z + v[i].w*v[i].w;
                }
                s  += __shfl_xor_sync(0xffffffffu, s, 1);
                s  += __shfl_xor_sync(0xffffffffu, s, 2);
                qq += __shfl_xor_sync(0xffffffffu, qq, 1);
                qq += __shfl_xor_sync(0xffffffffu, qq, 2);
                mu = s * (1.f/192.f);
                rs = rsqrtf(qq*(1.f/192.f) - mu*mu + 1e-5f);
            }
            #pragma unroll
            for (int i = 0; i < 12; i++) {
                int k = q*48 + i*4;
                float vv[4] = {v[i].x, v[i].y, v[i].z, v[i].w};
                #pragma unroll
                for (int e = 0; e < 4; e++) {
                    float z = vv[e];
                    if (do_ln)
                        z = fmaxf(0.f, (z - mu)*rs*__ldg(lng + L*HID + k + e)
                                        + __ldg(lnb + L*HID + k + e));
                    *(float2*)(sA + (k + e)*RA + 2*m) = make_float2(z, z);
                }
            }
        }
        __syncthreads();

        // ---- GEMM main: 3 LDS.128 + 8 FMA2 per kk ----
        {
            int half = t >> 8, th = t & 255;
            int tx = th & 7, ty = th >> 3;       // 8 n-groups x 32 m-pairs
            const float* sB = half ? sB1 : sB0;
            int nj = half ? (njA + 9) : njA;
            int w1 = tx*8;     int p1 = w1 + ((w1 >> 5) << 2);
            int w2 = tx*8 + 4; int p2 = w2 + ((w2 >> 5) << 2);
            ull acc[2][4] = {};
            #pragma unroll 4
            for (int kk = 0; kk < 192; kk++) {
                ulonglong2 av  = *(const ulonglong2*)(sA + kk*RA + ty*4);
                ulonglong2 b01 = *(const ulonglong2*)(sB + kk*RB + p1);
                ulonglong2 b23 = *(const ulonglong2*)(sB + kk*RB + p2);
                fma2(acc[0][0], av.x, b01.x); fma2(acc[0][1], av.x, b01.y);
                fma2(acc[0][2], av.x, b23.x); fma2(acc[0][3], av.x, b23.y);
                fma2(acc[1][0], av.y, b01.x); fma2(acc[1][1], av.y, b01.y);
                fma2(acc[1][2], av.y, b23.x); fma2(acc[1][3], av.y, b23.y);
            }
            int n0 = nj*64;
            if (nj < 15) {
                #pragma unroll
                for (int mi = 0; mi < 2; mi++) {
                    float* yp = g_Y + (size_t)(m0 + ty*2 + mi)*NAUG + n0 + tx*8;
                    float2 c0 = up2(acc[mi][0]), c1 = up2(acc[mi][1]);
                    float2 c2 = up2(acc[mi][2]), c3 = up2(acc[mi][3]);
                    *(float4*)yp       = make_float4(c0.x, c0.y, c1.x, c1.y);
                    *(float4*)(yp + 4) = make_float4(c2.x, c2.y, c3.x, c3.y);
                }
            } else {
                int ob2 = n0 - 960 + tx*8;
                float4 cb0 = *(const float4*)(conv_b + L*HID + ob2);
                float4 cb1 = *(const float4*)(conv_b + L*HID + ob2 + 4);
                #pragma unroll
                for (int mi = 0; mi < 2; mi++) {
                    int row = m0 + ty*2 + mi;
                    float2 c0 = up2(acc[mi][0]), c1 = up2(acc[mi][1]);
                    float2 c2 = up2(acc[mi][2]), c3 = up2(acc[mi][3]);
                    float4 r0 = make_float4(c0.x + cb0.x, c0.y + cb0.y, c1.x + cb0.z, c1.y + cb0.w);
                    float4 r1 = make_float4(c2.x + cb1.x, c2.y + cb1.y, c3.x + cb1.z, c3.y + cb1.w);
                    if (do_ln) {
                        float4 h0v = ldcg4((const float4*)(hin + (size_t)row*HID + ob2));
                        float4 h1v = ldcg4((const float4*)(hin + (size_t)row*HID + ob2 + 4));
                        r0.x += h0v.x; r0.y += h0v.y; r0.z += h0v.z; r0.w += h0v.w;
                        r1.x += h1v.x; r1.y += h1v.y; r1.z += h1v.z; r1.w += h1v.w;
                    }
                    *(float4*)(hout + (size_t)row*HID + ob2)     = r0;
                    *(float4*)(hout + (size_t)row*HID + ob2 + 4) = r1;
                }
            }
        }
        gbar(144u*(2 + 2*L));

        // ---- escatter (t<384) + B-prefetch layer L+1 (t>=384) ----
        if (t < 384) {
            int g = t / 48, o4 = t - g*48;
            #pragma unroll
            for (int i = 0; i < 2; i++) {
                int e = b*8 + g + 1152*i;
                if (e < EE) {
                    int s = __ldg(ei + e), d = __ldg(ei + EE + e);
                    float4 a = __ldg((const float4*)(attr + e*4));
                    const float4* Ys = (const float4*)(g_Y + (size_t)s*NAUG);
                    float4 y0 = ldcg4(Ys + o4),       y1 = ldcg4(Ys + 48 + o4);
                    float4 y2 = ldcg4(Ys + 96 + o4),  y3 = ldcg4(Ys + 144 + o4);
                    float4 y4 = ldcg4(Ys + 192 + o4);
                    float4 v;
                    v.x = y4.x + a.x*y0.x + a.y*y1.x + a.z*y2.x + a.w*y3.x;
                    v.y = y4.y + a.x*y0.y + a.y*y1.y + a.z*y2.y + a.w*y3.y;
                    v.z = y4.z + a.x*y0.z + a.y*y1.z + a.z*y2.z + a.w*y3.z;
                    v.w = y4.w + a.x*y0.w + a.y*y1.w + a.z*y2.w + a.w*y3.w;
                    float* hp = hout + (size_t)d*HID + o4*4;
                    atomicAdd(hp+0, v.x); atomicAdd(hp+1, v.y);
                    atomicAdd(hp+2, v.z); atomicAdd(hp+3, v.w);
                }
            }
        } else if (L < NL - 1) {
            int li = t - 384;
            const float* Bm = g_B[L + 1];
            #pragma unroll 4
            for (int i = 0; i < 48; i++) {
                int f = li + 128*i;
                int tile = f / 3072, r = f - tile*3072;
                int kk = r >> 4, w4 = r & 15;
                int nj = tile ? (njA + 9) : njA;
                float4 v = __ldg((const float4*)(Bm + kk*NAUG + nj*64 + w4*4));
                int w = w4*4;
                float* dst = (tile ? sB1 : sB0) + kk*RB + w + ((w >> 5) << 2);
                *(float4*)dst = v;
            }
        }
        gbar(144u*(3 + 2*L));
    }

    // ---- phase: final LN + head (warp per row; h final = g_h0) ----
    {
        int w = t >> 5, l = t & 31;
        if (w < 8) {
            int r = b + 144*w;
            if (r < NN) {
                float v[6];
                #pragma unroll
                for (int j = 0; j < 6; j++) v[j] = __ldcg(g_h0 + r*HID + l + 32*j);
                float s = ((v[0]+v[1])+(v[2]+v[3]))+(v[4]+v[5]);
                float q = v[0]*v[0]+v[1]*v[1]+v[2]*v[2]+v[3]*v[3]+v[4]*v[4]+v[5]*v[5];
                #pragma unroll
                for (int o = 16; o > 0; o >>= 1) {
                    s += __shfl_xor_sync(0xffffffffu, s, o);
                    q += __shfl_xor_sync(0xffffffffu, q, o);
                }
                float mu = s * (1.f/192.f);
                float rs = rsqrtf(q*(1.f/192.f) - mu*mu + 1e-5f);
                float p0 = 0.f, p1 = 0.f;
                #pragma unroll
                for (int j = 0; j < 6; j++) {
                    int c = l + 32*j;
                    float z = fmaxf(0.f, (v[j] - mu)*rs*__ldg(lng + c) + __ldg(lnb + c));
                    p0 += z * __ldg(ow + c*2);
                    p1 += z * __ldg(ow + c*2 + 1);
                }
                #pragma unroll
                for (int o = 16; o > 0; o >>= 1) {
                    p0 += __shfl_xor_sync(0xffffffffu, p0, o);
                    p1 += __shfl_xor_sync(0xffffffffu, p1, o);
                }
                if (l == 0) {
                    out[r*2]     = p0 + __ldg(ob);
                    out[r*2 + 1] = p1 + __ldg(ob + 1);
                }
            }
        }
    }
}

// ---------------- launcher ----------------
extern "C" void kernel_launch(void* const* d_in, const int* in_sizes, int n_in,
                              void* d_out, int out_size) {
    const float* x       = (const float*)d_in[0];
    const int*   ei      = (const int*)  d_in[1];
    const float* attr    = (const float*)d_in[2];
    const float* cheb_w  = (const float*)d_in[4];
    const float* cheb_b  = (const float*)d_in[5];
    const float* eenc_w  = (const float*)d_in[6];
    const float* eenc_b  = (const float*)d_in[7];
    const float* nn1_w   = (const float*)d_in[8];
    const float* nn1_b   = (const float*)d_in[9];
    const float* nn2_w   = (const float*)d_in[10];
    const float* nn2_b   = (const float*)d_in[11];
    const float* root_w  = (const float*)d_in[12];
    const float* conv_b  = (const float*)d_in[13];
    const float* ln_g    = (const float*)d_in[14];
    const float* ln_b    = (const float*)d_in[15];
    const float* out_w   = (const float*)d_in[16];
    const float* out_b   = (const float*)d_in[17];
    float* out = (float*)d_out;

    cudaFuncSetAttribute(k_M,    cudaFuncAttributeMaxDynamicSharedMemorySize, SMEM_CHEB);
    cudaFuncSetAttribute(k_main, cudaFuncAttributeMaxDynamicSharedMemorySize, SMEM_MAIN);

    // launch 1: Mstack + cheb prep + barrier reset
    k_M<<<dim3(37, NL), 256, SMEM_CHEB>>>(nn2_w, nn2_b, eenc_w, eenc_b,
                                          nn1_w, nn1_b, root_w, ei, x);
    // launch 2: everything else, persistent with software grid barriers
    k_main<<<144, 512, SMEM_MAIN>>>(x, ei, attr, cheb_w, cheb_b, conv_b,
                                    ln_g, ln_b, out_w, out_b, out);
}

// round 13
// speedup vs baseline: 1.2398x; 1.1576x over previous
#include <cuda_runtime.h>

#define NN 1024
#define EE 2048
#define HID 192
#define KCH 5
#define NL 4
#define NAUG 1152
#define RSA 68
#define SMEM_MAIN ((192*RSA + 2*192*64)*4)         // 150528
#define SMEM_CHEB ((1024 + 16384 + 4096)*4)        // 86016

typedef unsigned long long ull;

// ---------------- device scratch (allocation-free) ----------------
__device__ float g_S[4*NN*4];
__device__ float g_h0[NN*HID];
__device__ float g_h1[NN*HID];
__device__ float g_Y[NN*NAUG];
__device__ float g_B[NL][HID*NAUG];   // [layer][k][n] fp32
__device__ unsigned g_bar;

// ---------------- helpers ----------------
__device__ __forceinline__ void fma2(ull &c, ull a, ull b) {
    asm("fma.rn.f32x2 %0, %1, %2, %0;" : "+l"(c) : "l"(a), "l"(b));
}
__device__ __forceinline__ ull pk2(float a) {
    ull r; asm("mov.b64 %0, {%1, %1};" : "=l"(r) : "f"(a)); return r;
}
__device__ __forceinline__ float2 up2(ull a) {
    float2 f; asm("mov.b64 {%0, %1}, %2;" : "=f"(f.x), "=f"(f.y) : "l"(a)); return f;
}
__device__ __forceinline__ float4 ldcg4(const float4* p) { return __ldcg(p); }
__device__ __forceinline__ void gbar(unsigned target) {
    __threadfence();
    __syncthreads();
    if (threadIdx.x == 0) {
        atomicAdd(&g_bar, 1u);
        while (*((volatile unsigned*)&g_bar) < target) __nanosleep(32);
    }
    __syncthreads();
}

// ---------------- k_M: Mstack fp32 (36x4 blocks) + cheb prep (block 36,0) ----------------
__global__ void __launch_bounds__(256) k_M(const float* __restrict__ nn2_w,
                                           const float* __restrict__ nn2_b,
                                           const float* __restrict__ eenc_w,
                                           const float* __restrict__ eenc_b,
                                           const float* __restrict__ nn1_w,
                                           const float* __restrict__ nn1_b,
                                           const float* __restrict__ root_w,
                                           const int* __restrict__ ei,
                                           const float* __restrict__ x) {
    int t = threadIdx.x;
    if (blockIdx.x == 0 && blockIdx.y == 0 && t == 0) g_bar = 0;   // reset grid barrier
    if (blockIdx.x == 36) {
        if (blockIdx.y != 0) return;
        extern __shared__ float dsm[];
        float* sdeg = dsm;
        float* sS   = dsm + 1024;
        float* sX   = dsm + 1024 + 16384;
        #pragma unroll
        for (int i = 0; i < 4; i++) sdeg[t + 256*i] = 0.f;
        #pragma unroll
        for (int i = 0; i < 64; i++) sS[t + 256*i] = 0.f;
        #pragma unroll
        for (int i = 0; i < 16; i++) sX[t + 256*i] = x[t + 256*i];
        __syncthreads();
        int s[8], d[8]; float w[8];
        #pragma unroll
        for (int j = 0; j < 8; j++) {
            int e = t*8 + j;
            s[j] = ei[e]; d[j] = ei[EE + e];
            atomicAdd(&sdeg[s[j]], 1.f);
        }
        __syncthreads();
        float dv[4];
        #pragma unroll
        for (int i = 0; i < 4; i++) dv[i] = sdeg[t + 256*i];
        __syncthreads();
        #pragma unroll
        for (int i = 0; i < 4; i++) sdeg[t + 256*i] = dv[i] > 0.f ? rsqrtf(dv[i]) : 0.f;
        __syncthreads();
        #pragma unroll
        for (int j = 0; j < 8; j++) w[j] = -sdeg[s[j]] * sdeg[d[j]];
        #pragma unroll
        for (int j = 0; j < 8; j++)
            #pragma unroll
            for (int c = 0; c < 4; c++)
                atomicAdd(&sS[d[j]*4 + c], w[j] * sX[s[j]*4 + c]);
        __syncthreads();
        #pragma unroll
        for (int j = 0; j < 8; j++)
            #pragma unroll
            for (int c = 0; c < 4; c++)
                atomicAdd(&sS[4096 + d[j]*4 + c], w[j] * sS[s[j]*4 + c]);
        __syncthreads();
        #pragma unroll
        for (int j = 0; j < 8; j++)
            #pragma unroll
            for (int c = 0; c < 4; c++)
                atomicAdd(&sS[8192 + d[j]*4 + c],
                          w[j] * (2.f*sS[4096 + s[j]*4 + c] - sX[s[j]*4 + c]));
        __syncthreads();
        #pragma unroll
        for (int j = 0; j < 8; j++)
            #pragma unroll
            for (int c = 0; c < 4; c++)
                atomicAdd(&sS[12288 + d[j]*4 + c],
                          w[j] * (2.f*sS[8192 + s[j]*4 + c] - sS[s[j]*4 + c]));
        __syncthreads();
        #pragma unroll
        for (int i = 0; i < 64; i++) g_S[t + 256*i] = sS[t + 256*i];
        return;
    }

    int i = blockIdx.y;
    __shared__ float2 sG[5*HID];
    if (t < HID) {
        float acc[5] = {0.f, 0.f, 0.f, 0.f, 0.f};
        const float* W = nn1_w + i*HID*HID;
        for (int j0 = 0; j0 < HID; j0++) {
            float w = W[j0*HID + t];
            acc[0] += eenc_w[j0]*w;
            acc[1] += eenc_w[HID + j0]*w;
            acc[2] += eenc_w[2*HID + j0]*w;
            acc[3] += eenc_w[3*HID + j0]*w;
            acc[4] += eenc_b[j0]*w;
        }
        acc[4] += nn1_b[i*HID + t];
        #pragma unroll
        for (int k = 0; k < 5; k++) sG[k*HID + t] = make_float2(acc[k], acc[k]);
    }
    {
        int m = blockIdx.x*1024 + t*4;
        int j = m / HID, o = m - j*HID;
        float4 v = *(const float4*)(root_w + (size_t)i*HID*HID + m);
        *(float4*)(g_B[i] + j*NAUG + 5*HID + o) = v;
    }
    __syncthreads();

    int m4 = (blockIdx.x*256 + t) * 4;
    const float* W = nn2_w + (size_t)i * HID * (HID*HID);
    ull acc[5][2] = {};
    #pragma unroll 8
    for (int j = 0; j < HID; j++) {
        float4 v = __ldg((const float4*)(W + (size_t)j*(HID*HID) + m4));
        ull v01, v23;
        asm("mov.b64 %0, {%1, %2};" : "=l"(v01) : "f"(v.x), "f"(v.y));
        asm("mov.b64 %0, {%1, %2};" : "=l"(v23) : "f"(v.z), "f"(v.w));
        #pragma unroll
        for (int k = 0; k < 5; k++) {
            ull gk = *(const ull*)&sG[k*HID + j];
            fma2(acc[k][0], gk, v01);
            fma2(acc[k][1], gk, v23);
        }
    }
    float4 b = __ldg((const float4*)(nn2_b + (size_t)i*(HID*HID) + m4));
    float2 a40 = up2(acc[4][0]), a41 = up2(acc[4][1]);
    a40.x += b.x; a40.y += b.y; a41.x += b.z; a41.y += b.w;
    int j2 = m4 / HID;
    int o  = m4 - j2 * HID;
    float* dst = g_B[i] + j2*NAUG + o;
    #pragma unroll
    for (int k = 0; k < 4; k++) {
        *(float2*)(dst + k*HID)     = up2(acc[k][0]);
        *(float2*)(dst + k*HID + 2) = up2(acc[k][1]);
    }
    *(float2*)(dst + 4*HID)     = a40;
    *(float2*)(dst + 4*HID + 2) = a41;
}

// ---------------- persistent main kernel ----------------
__global__ void __launch_bounds__(512, 1)
k_main(const float* __restrict__ x, const int* __restrict__ ei,
       const float* __restrict__ attr,
       const float* __restrict__ cw, const float* __restrict__ cbb,
       const float* __restrict__ conv_b,
       const float* __restrict__ lng, const float* __restrict__ lnb,
       const float* __restrict__ ow, const float* __restrict__ ob,
       float* __restrict__ out) {
    extern __shared__ float sm[];
    float* sA  = sm;                 // [192][RSA] non-dup, [k][m]
    float* sB0 = sm + 192*RSA;       // [192][64]
    float* sB1 = sB0 + 192*64;
    int t = threadIdx.x, b = blockIdx.x;
    int m0  = (b & 15) * 64;
    int njA = b >> 4;                // 0..8 ; partner n-tile njA+9

    // ---- phase: cheb_out (t<384) + B-prefetch layer0 (t>=384) ----
    if (t < 384) {
        int g = t / 192, o = t - g*192;
        for (int i = 0; i < 4; i++) {
            int r = b*2 + g + 288*i;
            if (r < NN) {
                float acc = __ldg(cbb + o);
                #pragma unroll
                for (int c = 0; c < 4; c++) {
                    float xv = __ldg(x + r*4 + c);
                    float s1 = g_S[r*4+c],        s2 = g_S[4096 + r*4+c];
                    float s3 = g_S[8192 + r*4+c], s4 = g_S[12288 + r*4+c];
                    float t2 = 2.f*s2 - xv, t3 = 2.f*s3 - s1, t4 = 2.f*s4 - 2.f*s2 + xv;
                    acc += xv*__ldg(cw + c*HID + o)
                         + s1*__ldg(cw + (4+c)*HID + o)
                         + t2*__ldg(cw + (8+c)*HID + o)
                         + t3*__ldg(cw + (12+c)*HID + o)
                         + t4*__ldg(cw + (16+c)*HID + o);
                }
                g_h0[r*HID + o] = acc;
            }
        }
    } else {
        int li = t - 384;
        const float* Bm = g_B[0];
        #pragma unroll 4
        for (int i = 0; i < 48; i++) {
            int f = li + 128*i;
            int tile = f / 3072, r = f - tile*3072;
            int kk = r >> 4, w4 = r & 15;
            int nj = tile ? (njA + 9) : njA;
            float4 v = __ldg((const float4*)(Bm + kk*NAUG + nj*64 + w4*4));
            *(float4*)((tile ? sB1 : sB0) + kk*64 + w4*4) = v;
        }
    }
    gbar(144u);

    for (int L = 0; L < NL; L++) {
        const float* hin  = (L & 1) ? g_h1 : g_h0;
        float*       hout = (L & 1) ? g_h0 : g_h1;
        int do_ln = (L > 0);

        // ---- A prologue: 64 rows x 4 threads/row (t < 256), LN in registers ----
        if (t < 256) {
            int m = t >> 2, q = t & 3;
            const float4* rp = (const float4*)(hin + (size_t)(m0 + m)*HID) + q*12;
            float4 v[12];
            #pragma unroll
            for (int i = 0; i < 12; i++) v[i] = ldcg4(rp + i);
            float mu = 0.f, rs = 0.f;
            if (do_ln) {
                float s = 0.f, qq = 0.f;
                #pragma unroll
                for (int i = 0; i < 12; i++) {
                    s  += (v[i].x + v[i].y) + (v[i].z + v[i].w);
                    qq += v[i].x*v[i].x + v[i].y*v[i].y + v[i].z*v[i].z + v[i].w*v[i].w;
                }
                s  += __shfl_xor_sync(0xffffffffu, s, 1);
                s  += __shfl_xor_sync(0xffffffffu, s, 2);
                qq += __shfl_xor_sync(0xffffffffu, qq, 1);
                qq += __shfl_xor_sync(0xffffffffu, qq, 2);
                mu = s * (1.f/192.f);
                rs = rsqrtf(qq*(1.f/192.f) - mu*mu + 1e-5f);
            }
            #pragma unroll
            for (int i = 0; i < 12; i++) {
                int k = q*48 + i*4;
                float vv[4] = {v[i].x, v[i].y, v[i].z, v[i].w};
                #pragma unroll
                for (int e = 0; e < 4; e++) {
                    float z = vv[e];
                    if (do_ln)
                        z = fmaxf(0.f, (z - mu)*rs*__ldg(lng + L*HID + k + e)
                                        + __ldg(lnb + L*HID + k + e));
                    sA[(k + e)*RSA + m] = z;
                }
            }
        }
        __syncthreads();

        // ---- GEMM main: warp-uniform A broadcast; lane = 8m x 2n ----
        {
            int half = t >> 8, th = t & 255;
            int w = th >> 5, lane = th & 31;       // warp m-offset 8*w
            const float* sB = half ? sB1 : sB0;
            int nj = half ? (njA + 9) : njA;
            const float* aBase = sA + 8*w;
            const float* bBase = sB + 2*lane;
            ull acc[8] = {};
            #pragma unroll 4
            for (int kk = 0; kk < 192; kk++) {
                float4 a0 = *(const float4*)(aBase + kk*RSA);
                float4 a1 = *(const float4*)(aBase + kk*RSA + 4);
                ull bp = *(const ull*)(bBase + kk*64);
                fma2(acc[0], pk2(a0.x), bp);
                fma2(acc[1], pk2(a0.y), bp);
                fma2(acc[2], pk2(a0.z), bp);
                fma2(acc[3], pk2(a0.w), bp);
                fma2(acc[4], pk2(a1.x), bp);
                fma2(acc[5], pk2(a1.y), bp);
                fma2(acc[6], pk2(a1.z), bp);
                fma2(acc[7], pk2(a1.w), bp);
            }
            int n0 = nj*64;
            int nc = 2*lane;
            if (nj < 15) {
                #pragma unroll
                for (int i = 0; i < 8; i++)
                    *(float2*)(g_Y + (size_t)(m0 + 8*w + i)*NAUG + n0 + nc) = up2(acc[i]);
            } else {
                int ob2 = n0 - 960 + nc;
                float2 cbv = *(const float2*)(conv_b + L*HID + ob2);
                #pragma unroll
                for (int i = 0; i < 8; i++) {
                    int row = m0 + 8*w + i;
                    float2 r = up2(acc[i]);
                    r.x += cbv.x; r.y += cbv.y;
                    if (do_ln) {
                        float2 hv = __ldcg((const float2*)(hin + (size_t)row*HID + ob2));
                        r.x += hv.x; r.y += hv.y;
                    }
                    *(float2*)(hout + (size_t)row*HID + ob2) = r;
                }
            }
        }
        gbar(144u*(2 + 2*L));

        // ---- escatter (t<384) + B-prefetch layer L+1 (t>=384) ----
        if (t < 384) {
            int g = t / 48, o4 = t - g*48;
            #pragma unroll
            for (int i = 0; i < 2; i++) {
                int e = b*8 + g + 1152*i;
                if (e < EE) {
                    int s = __ldg(ei + e), d = __ldg(ei + EE + e);
                    float4 a = __ldg((const float4*)(attr + e*4));
                    const float4* Ys = (const float4*)(g_Y + (size_t)s*NAUG);
                    float4 y0 = ldcg4(Ys + o4),       y1 = ldcg4(Ys + 48 + o4);
                    float4 y2 = ldcg4(Ys + 96 + o4),  y3 = ldcg4(Ys + 144 + o4);
                    float4 y4 = ldcg4(Ys + 192 + o4);
                    float4 v;
                    v.x = y4.x + a.x*y0.x + a.y*y1.x + a.z*y2.x + a.w*y3.x;
                    v.y = y4.y + a.x*y0.y + a.y*y1.y + a.z*y2.y + a.w*y3.y;
                    v.z = y4.z + a.x*y0.z + a.y*y1.z + a.z*y2.z + a.w*y3.z;
                    v.w = y4.w + a.x*y0.w + a.y*y1.w + a.z*y2.w + a.w*y3.w;
                    float* hp = hout + (size_t)d*HID + o4*4;
                    atomicAdd(hp+0, v.x); atomicAdd(hp+1, v.y);
                    atomicAdd(hp+2, v.z); atomicAdd(hp+3, v.w);
                }
            }
        } else if (L < NL - 1) {
            int li = t - 384;
            const float* Bm = g_B[L + 1];
            #pragma unroll 4
            for (int i = 0; i < 48; i++) {
                int f = li + 128*i;
                int tile = f / 3072, r = f - tile*3072;
                int kk = r >> 4, w4 = r & 15;
                int nj = tile ? (njA + 9) : njA;
                float4 v = __ldg((const float4*)(Bm + kk*NAUG + nj*64 + w4*4));
                *(float4*)((tile ? sB1 : sB0) + kk*64 + w4*4) = v;
            }
        }
        gbar(144u*(3 + 2*L));
    }

    // ---- phase: final LN + head (warp per row; h final = g_h0) ----
    {
        int w = t >> 5, l = t & 31;
        if (w < 8) {
            int r = b + 144*w;
            if (r < NN) {
                float v[6];
                #pragma unroll
                for (int j = 0; j < 6; j++) v[j] = __ldcg(g_h0 + r*HID + l + 32*j);
                float s = ((v[0]+v[1])+(v[2]+v[3]))+(v[4]+v[5]);
                float q = v[0]*v[0]+v[1]*v[1]+v[2]*v[2]+v[3]*v[3]+v[4]*v[4]+v[5]*v[5];
                #pragma unroll
                for (int o = 16; o > 0; o >>= 1) {
                    s += __shfl_xor_sync(0xffffffffu, s, o);
                    q += __shfl_xor_sync(0xffffffffu, q, o);
                }
                float mu = s * (1.f/192.f);
                float rs = rsqrtf(q*(1.f/192.f) - mu*mu + 1e-5f);
                float p0 = 0.f, p1 = 0.f;
                #pragma unroll
                for (int j = 0; j < 6; j++) {
                    int c = l + 32*j;
                    float z = fmaxf(0.f, (v[j] - mu)*rs*__ldg(lng + c) + __ldg(lnb + c));
                    p0 += z * __ldg(ow + c*2);
                    p1 += z * __ldg(ow + c*2 + 1);
                }
                #pragma unroll
                for (int o = 16; o > 0; o >>= 1) {
                    p0 += __shfl_xor_sync(0xffffffffu, p0, o);
                    p1 += __shfl_xor_sync(0xffffffffu, p1, o);
                }
                if (l == 0) {
                    out[r*2]     = p0 + __ldg(ob);
                    out[r*2 + 1] = p1 + __ldg(ob + 1);
                }
            }
        }
    }
}

// ---------------- launcher ----------------
extern "C" void kernel_launch(void* const* d_in, const int* in_sizes, int n_in,
                              void* d_out, int out_size) {
    const float* x       = (const float*)d_in[0];
    const int*   ei      = (const int*)  d_in[1];
    const float* attr    = (const float*)d_in[2];
    const float* cheb_w  = (const float*)d_in[4];
    const float* cheb_b  = (const float*)d_in[5];
    const float* eenc_w  = (const float*)d_in[6];
    const float* eenc_b  = (const float*)d_in[7];
    const float* nn1_w   = (const float*)d_in[8];
    const float* nn1_b   = (const float*)d_in[9];
    const float* nn2_w   = (const float*)d_in[10];
    const float* nn2_b   = (const float*)d_in[11];
    const float* root_w  = (const float*)d_in[12];
    const float* conv_b  = (const float*)d_in[13];
    const float* ln_g    = (const float*)d_in[14];
    const float* ln_b    = (const float*)d_in[15];
    const float* out_w   = (const float*)d_in[16];
    const float* out_b   = (const float*)d_in[17];
    float* out = (float*)d_out;

    cudaFuncSetAttribute(k_M,    cudaFuncAttributeMaxDynamicSharedMemorySize, SMEM_CHEB);
    cudaFuncSetAttribute(k_main, cudaFuncAttributeMaxDynamicSharedMemorySize, SMEM_MAIN);

    // launch 1: Mstack + cheb prep + barrier reset
    k_M<<<dim3(37, NL), 256, SMEM_CHEB>>>(nn2_w, nn2_b, eenc_w, eenc_b,
                                          nn1_w, nn1_b, root_w, ei, x);
    // launch 2: everything else, persistent with software grid barriers
    k_main<<<144, 512, SMEM_MAIN>>>(x, ei, attr, cheb_w, cheb_b, conv_b,
                                    ln_g, ln_b, out_w, out_b, out);
}

// round 14
// speedup vs baseline: 1.2423x; 1.0020x over previous
#include <cuda_runtime.h>

#define NN 1024
#define EE 2048
#define HID 192
#define KCH 5
#define NL 4
#define NAUG 1152
#define RSA 68
#define SMEM_MAIN ((192*RSA + 2*192*64)*4)         // 150528
#define SMEM_CHEB ((1024 + 16384 + 4096)*4)        // 86016

typedef unsigned long long ull;

// ---------------- device scratch (allocation-free) ----------------
__device__ float g_S[4*NN*4];
__device__ float g_h0[NN*HID];
__device__ float g_h1[NN*HID];
__device__ float g_Y[NN*NAUG];
__device__ float g_B[NL][HID*NAUG];   // [layer][k][n] fp32
__device__ unsigned g_bar;

// ---------------- helpers ----------------
__device__ __forceinline__ void fma2(ull &c, ull a, ull b) {
    asm("fma.rn.f32x2 %0, %1, %2, %0;" : "+l"(c) : "l"(a), "l"(b));
}
__device__ __forceinline__ ull pk2(float a) {
    ull r; asm("mov.b64 %0, {%1, %1};" : "=l"(r) : "f"(a)); return r;
}
__device__ __forceinline__ float2 up2(ull a) {
    float2 f; asm("mov.b64 {%0, %1}, %2;" : "=f"(f.x), "=f"(f.y) : "l"(a)); return f;
}
__device__ __forceinline__ float4 ldcg4(const float4* p) { return __ldcg(p); }
__device__ __forceinline__ void gbar(unsigned target) {
    __threadfence();
    __syncthreads();
    if (threadIdx.x == 0) {
        atomicAdd(&g_bar, 1u);
        while (*((volatile unsigned*)&g_bar) < target) __nanosleep(32);
    }
    __syncthreads();
}

// ---------------- k_M: Mstack fp32 (36x4 blocks) + cheb prep (block 36,0) ----------------
__global__ void __launch_bounds__(256) k_M(const float* __restrict__ nn2_w,
                                           const float* __restrict__ nn2_b,
                                           const float* __restrict__ eenc_w,
                                           const float* __restrict__ eenc_b,
                                           const float* __restrict__ nn1_w,
                                           const float* __restrict__ nn1_b,
                                           const float* __restrict__ root_w,
                                           const int* __restrict__ ei,
                                           const float* __restrict__ x) {
    int t = threadIdx.x;
    if (blockIdx.x == 0 && blockIdx.y == 0 && t == 0) g_bar = 0;   // reset grid barrier
    if (blockIdx.x == 36) {
        if (blockIdx.y != 0) return;
        extern __shared__ float dsm[];
        float* sdeg = dsm;
        float* sS   = dsm + 1024;
        float* sX   = dsm + 1024 + 16384;
        #pragma unroll
        for (int i = 0; i < 4; i++) sdeg[t + 256*i] = 0.f;
        #pragma unroll
        for (int i = 0; i < 64; i++) sS[t + 256*i] = 0.f;
        #pragma unroll
        for (int i = 0; i < 16; i++) sX[t + 256*i] = x[t + 256*i];
        __syncthreads();
        int s[8], d[8]; float w[8];
        #pragma unroll
        for (int j = 0; j < 8; j++) {
            int e = t*8 + j;
            s[j] = ei[e]; d[j] = ei[EE + e];
            atomicAdd(&sdeg[s[j]], 1.f);
        }
        __syncthreads();
        float dv[4];
        #pragma unroll
        for (int i = 0; i < 4; i++) dv[i] = sdeg[t + 256*i];
        __syncthreads();
        #pragma unroll
        for (int i = 0; i < 4; i++) sdeg[t + 256*i] = dv[i] > 0.f ? rsqrtf(dv[i]) : 0.f;
        __syncthreads();
        #pragma unroll
        for (int j = 0; j < 8; j++) w[j] = -sdeg[s[j]] * sdeg[d[j]];
        #pragma unroll
        for (int j = 0; j < 8; j++)
            #pragma unroll
            for (int c = 0; c < 4; c++)
                atomicAdd(&sS[d[j]*4 + c], w[j] * sX[s[j]*4 + c]);
        __syncthreads();
        #pragma unroll
        for (int j = 0; j < 8; j++)
            #pragma unroll
            for (int c = 0; c < 4; c++)
                atomicAdd(&sS[4096 + d[j]*4 + c], w[j] * sS[s[j]*4 + c]);
        __syncthreads();
        #pragma unroll
        for (int j = 0; j < 8; j++)
            #pragma unroll
            for (int c = 0; c < 4; c++)
                atomicAdd(&sS[8192 + d[j]*4 + c],
                          w[j] * (2.f*sS[4096 + s[j]*4 + c] - sX[s[j]*4 + c]));
        __syncthreads();
        #pragma unroll
        for (int j = 0; j < 8; j++)
            #pragma unroll
            for (int c = 0; c < 4; c++)
                atomicAdd(&sS[12288 + d[j]*4 + c],
                          w[j] * (2.f*sS[8192 + s[j]*4 + c] - sS[s[j]*4 + c]));
        __syncthreads();
        #pragma unroll
        for (int i = 0; i < 64; i++) g_S[t + 256*i] = sS[t + 256*i];
        return;
    }

    int i = blockIdx.y;
    __shared__ float2 sG[5*HID];
    if (t < HID) {
        float acc[5] = {0.f, 0.f, 0.f, 0.f, 0.f};
        const float* W = nn1_w + i*HID*HID;
        for (int j0 = 0; j0 < HID; j0++) {
            float w = W[j0*HID + t];
            acc[0] += eenc_w[j0]*w;
            acc[1] += eenc_w[HID + j0]*w;
            acc[2] += eenc_w[2*HID + j0]*w;
            acc[3] += eenc_w[3*HID + j0]*w;
            acc[4] += eenc_b[j0]*w;
        }
        acc[4] += nn1_b[i*HID + t];
        #pragma unroll
        for (int k = 0; k < 5; k++) sG[k*HID + t] = make_float2(acc[k], acc[k]);
    }
    {
        int m = blockIdx.x*1024 + t*4;
        int j = m / HID, o = m - j*HID;
        float4 v = *(const float4*)(root_w + (size_t)i*HID*HID + m);
        *(float4*)(g_B[i] + j*NAUG + 5*HID + o) = v;
    }
    __syncthreads();

    int m4 = (blockIdx.x*256 + t) * 4;
    const float* W = nn2_w + (size_t)i * HID * (HID*HID);
    ull acc[5][2] = {};
    #pragma unroll 8
    for (int j = 0; j < HID; j++) {
        float4 v = __ldg((const float4*)(W + (size_t)j*(HID*HID) + m4));
        ull v01, v23;
        asm("mov.b64 %0, {%1, %2};" : "=l"(v01) : "f"(v.x), "f"(v.y));
        asm("mov.b64 %0, {%1, %2};" : "=l"(v23) : "f"(v.z), "f"(v.w));
        #pragma unroll
        for (int k = 0; k < 5; k++) {
            ull gk = *(const ull*)&sG[k*HID + j];
            fma2(acc[k][0], gk, v01);
            fma2(acc[k][1], gk, v23);
        }
    }
    float4 b = __ldg((const float4*)(nn2_b + (size_t)i*(HID*HID) + m4));
    float2 a40 = up2(acc[4][0]), a41 = up2(acc[4][1]);
    a40.x += b.x; a40.y += b.y; a41.x += b.z; a41.y += b.w;
    int j2 = m4 / HID;
    int o  = m4 - j2 * HID;
    float* dst = g_B[i] + j2*NAUG + o;
    #pragma unroll
    for (int k = 0; k < 4; k++) {
        *(float2*)(dst + k*HID)     = up2(acc[k][0]);
        *(float2*)(dst + k*HID + 2) = up2(acc[k][1]);
    }
    *(float2*)(dst + 4*HID)     = a40;
    *(float2*)(dst + 4*HID + 2) = a41;
}

// ---------------- persistent main kernel ----------------
__global__ void __launch_bounds__(512, 1)
k_main(const float* __restrict__ x, const int* __restrict__ ei,
       const float* __restrict__ attr,
       const float* __restrict__ cw, const float* __restrict__ cbb,
       const float* __restrict__ conv_b,
       const float* __restrict__ lng, const float* __restrict__ lnb,
       const float* __restrict__ ow, const float* __restrict__ ob,
       float* __restrict__ out) {
    extern __shared__ float sm[];
    float* sA  = sm;                 // [192][RSA] non-dup, [k][m]
    float* sB0 = sm + 192*RSA;       // [192][64]
    float* sB1 = sB0 + 192*64;
    int t = threadIdx.x, b = blockIdx.x;
    int m0  = (b & 15) * 64;
    int njA = b >> 4;                // 0..8 ; partner n-tile njA+9

    // ---- phase: cheb_out (t<384) + B-prefetch layer0 (t>=384) ----
    if (t < 384) {
        int g = t / 192, o = t - g*192;
        for (int i = 0; i < 4; i++) {
            int r = b*2 + g + 288*i;
            if (r < NN) {
                float acc = __ldg(cbb + o);
                #pragma unroll
                for (int c = 0; c < 4; c++) {
                    float xv = __ldg(x + r*4 + c);
                    float s1 = g_S[r*4+c],        s2 = g_S[4096 + r*4+c];
                    float s3 = g_S[8192 + r*4+c], s4 = g_S[12288 + r*4+c];
                    float t2 = 2.f*s2 - xv, t3 = 2.f*s3 - s1, t4 = 2.f*s4 - 2.f*s2 + xv;
                    acc += xv*__ldg(cw + c*HID + o)
                         + s1*__ldg(cw + (4+c)*HID + o)
                         + t2*__ldg(cw + (8+c)*HID + o)
                         + t3*__ldg(cw + (12+c)*HID + o)
                         + t4*__ldg(cw + (16+c)*HID + o);
                }
                g_h0[r*HID + o] = acc;
            }
        }
    } else {
        int li = t - 384;
        const float* Bm = g_B[0];
        #pragma unroll 4
        for (int i = 0; i < 48; i++) {
            int f = li + 128*i;
            int tile = f / 3072, r = f - tile*3072;
            int kk = r >> 4, w4 = r & 15;
            int nj = tile ? (njA + 9) : njA;
            float4 v = __ldg((const float4*)(Bm + kk*NAUG + nj*64 + w4*4));
            *(float4*)((tile ? sB1 : sB0) + kk*64 + w4*4) = v;
        }
    }
    gbar(144u);

    for (int L = 0; L < NL; L++) {
        const float* hin  = (L & 1) ? g_h1 : g_h0;
        float*       hout = (L & 1) ? g_h0 : g_h1;
        int do_ln = (L > 0);

        // ---- A prologue: 64 rows x 4 threads/row (t < 256), LN in registers ----
        if (t < 256) {
            int m = t >> 2, q = t & 3;
            const float4* rp = (const float4*)(hin + (size_t)(m0 + m)*HID) + q*12;
            float4 v[12];
            #pragma unroll
            for (int i = 0; i < 12; i++) v[i] = ldcg4(rp + i);
            float mu = 0.f, rs = 0.f;
            if (do_ln) {
                float s = 0.f, qq = 0.f;
                #pragma unroll
                for (int i = 0; i < 12; i++) {
                    s  += (v[i].x + v[i].y) + (v[i].z + v[i].w);
                    qq += v[i].x*v[i].x + v[i].y*v[i].y + v[i].z*v[i].z + v[i].w*v[i].w;
                }
                s  += __shfl_xor_sync(0xffffffffu, s, 1);
                s  += __shfl_xor_sync(0xffffffffu, s, 2);
                qq += __shfl_xor_sync(0xffffffffu, qq, 1);
                qq += __shfl_xor_sync(0xffffffffu, qq, 2);
                mu = s * (1.f/192.f);
                rs = rsqrtf(qq*(1.f/192.f) - mu*mu + 1e-5f);
            }
            #pragma unroll
            for (int i = 0; i < 12; i++) {
                int k = q*48 + i*4;
                float vv[4] = {v[i].x, v[i].y, v[i].z, v[i].w};
                #pragma unroll
                for (int e = 0; e < 4; e++) {
                    float z = vv[e];
                    if (do_ln)
                        z = fmaxf(0.f, (z - mu)*rs*__ldg(lng + L*HID + k + e)
                                        + __ldg(lnb + L*HID + k + e));
                    sA[(k + e)*RSA + m] = z;
                }
            }
        }
        __syncthreads();

        // ---- GEMM main: warp-uniform A broadcast; lane = 8m x 2n ----
        {
            int half = t >> 8, th = t & 255;
            int w = th >> 5, lane = th & 31;       // warp m-offset 8*w
            const float* sB = half ? sB1 : sB0;
            int nj = half ? (njA + 9) : njA;
            const float* aBase = sA + 8*w;
            const float* bBase = sB + 2*lane;
            ull acc[8] = {};
            #pragma unroll 4
            for (int kk = 0; kk < 192; kk++) {
                float4 a0 = *(const float4*)(aBase + kk*RSA);
                float4 a1 = *(const float4*)(aBase + kk*RSA + 4);
                ull bp = *(const ull*)(bBase + kk*64);
                fma2(acc[0], pk2(a0.x), bp);
                fma2(acc[1], pk2(a0.y), bp);
                fma2(acc[2], pk2(a0.z), bp);
                fma2(acc[3], pk2(a0.w), bp);
                fma2(acc[4], pk2(a1.x), bp);
                fma2(acc[5], pk2(a1.y), bp);
                fma2(acc[6], pk2(a1.z), bp);
                fma2(acc[7], pk2(a1.w), bp);
            }
            int n0 = nj*64;
            int nc = 2*lane;
            if (nj < 15) {
                #pragma unroll
                for (int i = 0; i < 8; i++)
                    *(float2*)(g_Y + (size_t)(m0 + 8*w + i)*NAUG + n0 + nc) = up2(acc[i]);
            } else {
                int ob2 = n0 - 960 + nc;
                float2 cbv = *(const float2*)(conv_b + L*HID + ob2);
                #pragma unroll
                for (int i = 0; i < 8; i++) {
                    int row = m0 + 8*w + i;
                    float2 r = up2(acc[i]);
                    r.x += cbv.x; r.y += cbv.y;
                    if (do_ln) {
                        float2 hv = __ldcg((const float2*)(hin + (size_t)row*HID + ob2));
                        r.x += hv.x; r.y += hv.y;
                    }
                    *(float2*)(hout + (size_t)row*HID + ob2) = r;
                }
            }
        }
        gbar(144u*(2 + 2*L));

        // ---- escatter (t<384) + B-prefetch layer L+1 (t>=384) ----
        if (t < 384) {
            int g = t / 48, o4 = t - g*48;
            #pragma unroll
            for (int i = 0; i < 2; i++) {
                int e = b*8 + g + 1152*i;
                if (e < EE) {
                    int s = __ldg(ei + e), d = __ldg(ei + EE + e);
                    float4 a = __ldg((const float4*)(attr + e*4));
                    const float4* Ys = (const float4*)(g_Y + (size_t)s*NAUG);
                    float4 y0 = ldcg4(Ys + o4),       y1 = ldcg4(Ys + 48 + o4);
                    float4 y2 = ldcg4(Ys + 96 + o4),  y3 = ldcg4(Ys + 144 + o4);
                    float4 y4 = ldcg4(Ys + 192 + o4);
                    float4 v;
                    v.x = y4.x + a.x*y0.x + a.y*y1.x + a.z*y2.x + a.w*y3.x;
                    v.y = y4.y + a.x*y0.y + a.y*y1.y + a.z*y2.y + a.w*y3.y;
                    v.z = y4.z + a.x*y0.z + a.y*y1.z + a.z*y2.z + a.w*y3.z;
                    v.w = y4.w + a.x*y0.w + a.y*y1.w + a.z*y2.w + a.w*y3.w;
                    float* hp = hout + (size_t)d*HID + o4*4;
                    atomicAdd(hp+0, v.x); atomicAdd(hp+1, v.y);
                    atomicAdd(hp+2, v.z); atomicAdd(hp+3, v.w);
                }
            }
        } else if (L < NL - 1) {
            int li = t - 384;
            const float* Bm = g_B[L + 1];
            #pragma unroll 4
            for (int i = 0; i < 48; i++) {
                int f = li + 128*i;
                int tile = f / 3072, r = f - tile*3072;
                int kk = r >> 4, w4 = r & 15;
                int nj = tile ? (njA + 9) : njA;
                float4 v = __ldg((const float4*)(Bm + kk*NAUG + nj*64 + w4*4));
                *(float4*)((tile ? sB1 : sB0) + kk*64 + w4*4) = v;
            }
        }
        gbar(144u*(3 + 2*L));
    }

    // ---- phase: final LN + head (warp per row; h final = g_h0) ----
    {
        int w = t >> 5, l = t & 31;
        if (w < 8) {
            int r = b + 144*w;
            if (r < NN) {
                float v[6];
                #pragma unroll
                for (int j = 0; j < 6; j++) v[j] = __ldcg(g_h0 + r*HID + l + 32*j);
                float s = ((v[0]+v[1])+(v[2]+v[3]))+(v[4]+v[5]);
                float q = v[0]*v[0]+v[1]*v[1]+v[2]*v[2]+v[3]*v[3]+v[4]*v[4]+v[5]*v[5];
                #pragma unroll
                for (int o = 16; o > 0; o >>= 1) {
                    s += __shfl_xor_sync(0xffffffffu, s, o);
                    q += __shfl_xor_sync(0xffffffffu, q, o);
                }
                float mu = s * (1.f/192.f);
                float rs = rsqrtf(q*(1.f/192.f) - mu*mu + 1e-5f);
                float p0 = 0.f, p1 = 0.f;
                #pragma unroll
                for (int j = 0; j < 6; j++) {
                    int c = l + 32*j;
                    float z = fmaxf(0.f, (v[j] - mu)*rs*__ldg(lng + c) + __ldg(lnb + c));
                    p0 += z * __ldg(ow + c*2);
                    p1 += z * __ldg(ow + c*2 + 1);
                }
                #pragma unroll
                for (int o = 16; o > 0; o >>= 1) {
                    p0 += __shfl_xor_sync(0xffffffffu, p0, o);
                    p1 += __shfl_xor_sync(0xffffffffu, p1, o);
                }
                if (l == 0) {
                    out[r*2]     = p0 + __ldg(ob);
                    out[r*2 + 1] = p1 + __ldg(ob + 1);
                }
            }
        }
    }
}

// ---------------- launcher ----------------
extern "C" void kernel_launch(void* const* d_in, const int* in_sizes, int n_in,
                              void* d_out, int out_size) {
    const float* x       = (const float*)d_in[0];
    const int*   ei      = (const int*)  d_in[1];
    const float* attr    = (const float*)d_in[2];
    const float* cheb_w  = (const float*)d_in[4];
    const float* cheb_b  = (const float*)d_in[5];
    const float* eenc_w  = (const float*)d_in[6];
    const float* eenc_b  = (const float*)d_in[7];
    const float* nn1_w   = (const float*)d_in[8];
    const float* nn1_b   = (const float*)d_in[9];
    const float* nn2_w   = (const float*)d_in[10];
    const float* nn2_b   = (const float*)d_in[11];
    const float* root_w  = (const float*)d_in[12];
    const float* conv_b  = (const float*)d_in[13];
    const float* ln_g    = (const float*)d_in[14];
    const float* ln_b    = (const float*)d_in[15];
    const float* out_w   = (const float*)d_in[16];
    const float* out_b   = (const float*)d_in[17];
    float* out = (float*)d_out;

    cudaFuncSetAttribute(k_M,    cudaFuncAttributeMaxDynamicSharedMemorySize, SMEM_CHEB);
    cudaFuncSetAttribute(k_main, cudaFuncAttributeMaxDynamicSharedMemorySize, SMEM_MAIN);

    // launch 1: Mstack + cheb prep + barrier reset
    k_M<<<dim3(37, NL), 256, SMEM_CHEB>>>(nn2_w, nn2_b, eenc_w, eenc_b,
                                          nn1_w, nn1_b, root_w, ei, x);
    // launch 2: everything else, persistent with software grid barriers
    k_main<<<144, 512, SMEM_MAIN>>>(x, ei, attr, cheb_w, cheb_b, conv_b,
                                    ln_g, ln_b, out_w, out_b, out);
}